// round 12
// baseline (speedup 1.0000x reference)
#include <cuda_runtime.h>
#include <cuda_bf16.h>
#include <cstdint>

// Problem constants
#define Bz   32
#define Nseq 512
#define Dm   1024
#define Hh   16
#define DHd  64
#define Mtot (Bz * Nseq)          // 16384
#define NT3  (3 * Dm)             // 3072

typedef unsigned long long u64;
typedef unsigned int u32;

// ---------------------------------------------------------------------------
// Scratch (allocation-free rule: __device__ globals)
// ---------------------------------------------------------------------------
__device__ float g_gate[2][Bz * Dm];
__device__ float g_upd_v[Mtot * Dm];
__device__ float g_upd_t[Mtot * Dm];

// bf16-split operands for tensor-core GEMMs
__device__ __nv_bfloat16 g_ah[2][Mtot * Dm];   // relu(x) hi   (kqv A)
__device__ __nv_bfloat16 g_al[2][Mtot * Dm];   // relu(x) lo
__device__ __nv_bfloat16 g_ph[2][Mtot * Dm];   // (x+upd) hi   (proj A)
__device__ __nv_bfloat16 g_pl[2][Mtot * Dm];   // (x+upd) lo
__device__ __nv_bfloat16 g_wk_h[2][NT3 * Dm];  // W_v / W_t transposed [n][k] hi
__device__ __nv_bfloat16 g_wk_l[2][NT3 * Dm];
__device__ __nv_bfloat16 g_wo_h[2][Dm * Dm];   // W_vo / W_to transposed [n][k] hi
__device__ __nv_bfloat16 g_wo_l[2][Dm * Dm];

// Attention operands, per-head layout [bh][tok][64] (gated/masked, bf16 split)
#define NBH (Bz * Hh)
__device__ __nv_bfloat16 g_qh[2][NBH * Nseq * DHd];
__device__ __nv_bfloat16 g_ql[2][NBH * Nseq * DHd];
__device__ __nv_bfloat16 g_kh[2][NBH * Nseq * DHd];
__device__ __nv_bfloat16 g_kl[2][NBH * Nseq * DHd];
__device__ __nv_bfloat16 g_vh[2][NBH * Nseq * DHd];
__device__ __nv_bfloat16 g_vl[2][NBH * Nseq * DHd];
// V transposed per head: [bh][dh][tok]
__device__ __nv_bfloat16 g_vth[2][NBH * DHd * Nseq];
__device__ __nv_bfloat16 g_vtl[2][NBH * DHd * Nseq];

// ---------------------------------------------------------------------------
// Small helpers
// ---------------------------------------------------------------------------
__device__ __forceinline__ float fexp(float x) {
    x = fmaxf(x, -80.0f);
    float z  = fmaf(x, 1.4426950408889634f, 12582912.0f);
    int   ni = __float_as_int(z) - 0x4B400000;
    float nf = (float)ni;
    float r  = fmaf(nf, -0.693359375f, x);
    r        = fmaf(nf, 2.12194440e-4f, r);
    float p  = 1.9875691500e-4f;
    p = fmaf(p, r, 1.3981999507e-3f);
    p = fmaf(p, r, 8.3334519073e-3f);
    p = fmaf(p, r, 4.1665795894e-2f);
    p = fmaf(p, r, 1.6666665459e-1f);
    p = fmaf(p, r, 5.0000001201e-1f);
    float e = fmaf(r * r, p, r) + 1.0f;
    return __int_as_float(__float_as_int(e) + (ni << 23));
}

__device__ __forceinline__ void bsplit(float a, unsigned short& h, unsigned short& l) {
    __nv_bfloat16 hb = __float2bfloat16_rn(a);
    float lo = a - __bfloat162float(hb);
    __nv_bfloat16 lb = __float2bfloat16_rn(lo);
    h = __bfloat16_as_ushort(hb);
    l = __bfloat16_as_ushort(lb);
}
__device__ __forceinline__ u32 pkbf(unsigned short a, unsigned short b) {
    return ((u32)b << 16) | (u32)a;
}
__device__ __forceinline__ void split_pair(float x, float y, u32& hp, u32& lp) {
    unsigned short hx, lx, hy, ly;
    bsplit(x, hx, lx);
    bsplit(y, hy, ly);
    hp = pkbf(hx, hy);
    lp = pkbf(lx, ly);
}

__device__ __forceinline__ u32 s2u(const void* p) {
    u32 a; asm("{ .reg .u64 t; cvta.to.shared.u64 t,%1; cvt.u32.u64 %0,t; }" : "=r"(a) : "l"(p));
    return a;
}
#define SWZ(o) ((o) ^ (((o) >> 3) & 0x70))

// mma.sync / ldmatrix / cp.async wrappers (base-arch features)
__device__ __forceinline__ void ldsm4(u32& r0, u32& r1, u32& r2, u32& r3, u32 addr) {
    asm volatile("ldmatrix.sync.aligned.m8n8.x4.shared.b16 {%0,%1,%2,%3}, [%4];"
                 : "=r"(r0), "=r"(r1), "=r"(r2), "=r"(r3) : "r"(addr));
}
__device__ __forceinline__ void mma16816(float* d, const u32* a, u32 b0, u32 b1) {
    asm volatile(
        "mma.sync.aligned.m16n8k16.row.col.f32.bf16.bf16.f32 "
        "{%0,%1,%2,%3},{%4,%5,%6,%7},{%8,%9},{%0,%1,%2,%3};"
        : "+f"(d[0]), "+f"(d[1]), "+f"(d[2]), "+f"(d[3])
        : "r"(a[0]), "r"(a[1]), "r"(a[2]), "r"(a[3]), "r"(b0), "r"(b1));
}
__device__ __forceinline__ void cpa16(u32 saddr, const void* g) {
    asm volatile("cp.async.cg.shared.global [%0], [%1], 16;" :: "r"(saddr), "l"(g) : "memory");
}
__device__ __forceinline__ void cpa_commit() {
    asm volatile("cp.async.commit_group;" ::: "memory");
}
__device__ __forceinline__ void cpa_wait1() {
    asm volatile("cp.async.wait_group 1;" ::: "memory");
}
__device__ __forceinline__ void cpa_wait0() {
    asm volatile("cp.async.wait_group 0;" ::: "memory");
}

// ---------------------------------------------------------------------------
// Kernel 1: fused masked-mean + gate. grid (Bz, 2), block 256.
// ---------------------------------------------------------------------------
__global__ __launch_bounds__(256) void meangate_kernel(
    const float* __restrict__ v, const float* __restrict__ t,
    const float* __restrict__ vm, const float* __restrict__ tm,
    const float* __restrict__ W_v4t, const float* __restrict__ b_v4t,
    const float* __restrict__ W_t4v, const float* __restrict__ b_t4v)
{
    const int zg = blockIdx.y;
    const int b  = blockIdx.x;
    const float* X    = (zg ^ 1) ? t  : v;
    const float* mk   = (zg ^ 1) ? tm : vm;
    const float* W    = zg ? W_v4t : W_t4v;
    const float* bias = zg ? b_v4t : b_t4v;

    __shared__ float s_mean[Dm];
    __shared__ float s_mk[Nseq];
    __shared__ float s_red[256];

    const int tid = threadIdx.x;
    float csum = 0.f;
    for (int n = tid; n < Nseq; n += 256) {
        float m = mk[b * Nseq + n];
        s_mk[n] = m;
        csum += m;
    }
    s_red[tid] = csum;
    __syncthreads();
    for (int s = 128; s > 0; s >>= 1) {
        if (tid < s) s_red[tid] += s_red[tid + s];
        __syncthreads();
    }
    const float inv = 1.0f / s_red[0];

    float4 acc = make_float4(0.f, 0.f, 0.f, 0.f);
    const float* Xb = X + (size_t)b * Nseq * Dm + tid * 4;
    for (int n = 0; n < Nseq; n++) {
        const float m = s_mk[n];
        float4 xv = *reinterpret_cast<const float4*>(Xb + (size_t)n * Dm);
        acc.x = fmaf(xv.x, m, acc.x); acc.y = fmaf(xv.y, m, acc.y);
        acc.z = fmaf(xv.z, m, acc.z); acc.w = fmaf(xv.w, m, acc.w);
    }
    s_mean[tid * 4 + 0] = fmaxf(acc.x * inv, 0.f);
    s_mean[tid * 4 + 1] = fmaxf(acc.y * inv, 0.f);
    s_mean[tid * 4 + 2] = fmaxf(acc.z * inv, 0.f);
    s_mean[tid * 4 + 3] = fmaxf(acc.w * inv, 0.f);
    __syncthreads();

    float a[4];
#pragma unroll
    for (int k = 0; k < 4; k++) a[k] = bias[k * 256 + tid];
    for (int i = 0; i < Dm; i++) {
        const float sm = s_mean[i];
        const float* Wr = W + (size_t)i * Dm + tid;
#pragma unroll
        for (int k = 0; k < 4; k++)
            a[k] = fmaf(sm, Wr[k * 256], a[k]);
    }
#pragma unroll
    for (int k = 0; k < 4; k++) {
        float s = 1.0f / (1.0f + fexp(-fabsf(a[k])));
        g_gate[zg][b * Dm + k * 256 + tid] = (a[k] >= 0.f) ? s : (1.0f - s);
    }
}

// ---------------------------------------------------------------------------
// Conversion kernels
// ---------------------------------------------------------------------------
__global__ __launch_bounds__(256) void conv_a_kqv(
    const float* __restrict__ v, const float* __restrict__ t)
{
    const int z = blockIdx.y;
    const float* X = z ? t : v;
    size_t i = ((size_t)blockIdx.x * 256 + threadIdx.x) * 8;
    float4 a0 = *reinterpret_cast<const float4*>(X + i);
    float4 a1 = *reinterpret_cast<const float4*>(X + i + 4);
    float f[8] = {fmaxf(a0.x,0.f), fmaxf(a0.y,0.f), fmaxf(a0.z,0.f), fmaxf(a0.w,0.f),
                  fmaxf(a1.x,0.f), fmaxf(a1.y,0.f), fmaxf(a1.z,0.f), fmaxf(a1.w,0.f)};
    unsigned short h[8], l[8];
#pragma unroll
    for (int q = 0; q < 8; q++) bsplit(f[q], h[q], l[q]);
    uint4 H = make_uint4(pkbf(h[0],h[1]), pkbf(h[2],h[3]), pkbf(h[4],h[5]), pkbf(h[6],h[7]));
    uint4 L = make_uint4(pkbf(l[0],l[1]), pkbf(l[2],l[3]), pkbf(l[4],l[5]), pkbf(l[6],l[7]));
    *reinterpret_cast<uint4*>(&g_ah[z][i]) = H;
    *reinterpret_cast<uint4*>(&g_al[z][i]) = L;
}

__global__ __launch_bounds__(256) void conv_a_proj(
    const float* __restrict__ v, const float* __restrict__ t)
{
    const int z = blockIdx.y;
    const float* X = z ? t : v;
    const float* U = z ? g_upd_t : g_upd_v;
    size_t i = ((size_t)blockIdx.x * 256 + threadIdx.x) * 8;
    float4 a0 = *reinterpret_cast<const float4*>(X + i);
    float4 a1 = *reinterpret_cast<const float4*>(X + i + 4);
    float4 u0 = *reinterpret_cast<const float4*>(U + i);
    float4 u1 = *reinterpret_cast<const float4*>(U + i + 4);
    float f[8] = {a0.x+u0.x, a0.y+u0.y, a0.z+u0.z, a0.w+u0.w,
                  a1.x+u1.x, a1.y+u1.y, a1.z+u1.z, a1.w+u1.w};
    unsigned short h[8], l[8];
#pragma unroll
    for (int q = 0; q < 8; q++) bsplit(f[q], h[q], l[q]);
    uint4 H = make_uint4(pkbf(h[0],h[1]), pkbf(h[2],h[3]), pkbf(h[4],h[5]), pkbf(h[6],h[7]));
    uint4 L = make_uint4(pkbf(l[0],l[1]), pkbf(l[2],l[3]), pkbf(l[4],l[5]), pkbf(l[6],l[7]));
    *reinterpret_cast<uint4*>(&g_ph[z][i]) = H;
    *reinterpret_cast<uint4*>(&g_pl[z][i]) = L;
}

// Weight transpose + split, both weight sets in one launch.
__global__ void conv_wt(const float* __restrict__ Wv, const float* __restrict__ Wt,
                        const float* __restrict__ Wvo, const float* __restrict__ Wto)
{
    const int mode = blockIdx.z >> 1;
    const int z    = blockIdx.z & 1;
    const int N = mode ? Dm : NT3;
    if (blockIdx.x * 32 >= (unsigned)N) return;
    const float* W = mode ? (z ? Wto : Wvo) : (z ? Wt : Wv);
    __nv_bfloat16* Th = mode ? g_wo_h[z] : g_wk_h[z];
    __nv_bfloat16* Tl = mode ? g_wo_l[z] : g_wk_l[z];

    __shared__ float s[32][33];
    const int n0 = blockIdx.x * 32;
    const int k0 = blockIdx.y * 32;
    const int tx = threadIdx.x, ty = threadIdx.y;
    for (int dy = ty; dy < 32; dy += 8)
        s[dy][tx] = W[(size_t)(k0 + dy) * N + n0 + tx];
    __syncthreads();
    for (int dy = ty; dy < 32; dy += 8) {
        float a = s[tx][dy];
        unsigned short h, l;
        bsplit(a, h, l);
        size_t o = (size_t)(n0 + dy) * Dm + k0 + tx;
        Th[o] = __ushort_as_bfloat16(h);
        Tl[o] = __ushort_as_bfloat16(l);
    }
}

// V transpose per head: [bh][tok][dh] -> [bh][dh][tok], 64-token tiles
__global__ __launch_bounds__(256) void vt_kernel()
{
    const int z   = blockIdx.z;
    const int bh  = blockIdx.y;
    const int kt0 = blockIdx.x * 64;
    __shared__ unsigned short s[64][68];
    const int tid = threadIdx.x;
#pragma unroll
    for (int hl = 0; hl < 2; hl++) {
        const __nv_bfloat16* in = (hl ? g_vl[z] : g_vh[z]) + (size_t)bh * Nseq * DHd;
        __nv_bfloat16* op       = (hl ? g_vtl[z] : g_vth[z]) + (size_t)bh * DHd * Nseq;
        const u32* in32 = reinterpret_cast<const u32*>(in);
        u32* out32 = reinterpret_cast<u32*>(op);
        if (hl) __syncthreads();
        for (int i = tid; i < 64 * 32; i += 256) {
            const int tok = i >> 5, dc = i & 31;
            *reinterpret_cast<u32*>(&s[tok][dc * 2]) = in32[(size_t)(kt0 + tok) * 32 + dc];
        }
        __syncthreads();
        for (int i = tid; i < 64 * 32; i += 256) {
            const int dh = i >> 5, t2 = i & 31;
            const u32 w = ((u32)s[2 * t2 + 1][dh] << 16) | (u32)s[2 * t2][dh];
            out32[(size_t)dh * (Nseq / 2) + (kt0 >> 1) + t2] = w;
        }
    }
}

// ---------------------------------------------------------------------------
// Tensor-core GEMM (mma.sync HMMA). CTA tile 128x128, 8 warps (2m x 4n), warp
// tile 64x32, m16n8k16 bf16->fp32, 3-term split: AhBh+AhBl+AlBh.
// 3-stage cp.async pipeline (3 x 64KB smem), ONE __syncthreads per K-chunk:
//   wait(c) -> sync -> issue loads(c+2) -> compute(c).
// Buffer-reuse safety: sync at iter c guarantees all warps finished reading
// buffer (c-1)%3 == (c+2)%3 before it is overwritten.
// mode 0: kqv -> gated/masked bf16-split Q/K/V per-head; mode 1: proj -> fp32.
// grid (NT/128, 128, 2), block 256.
// ---------------------------------------------------------------------------
#define SMEM_MMA (3 * 65536)
extern __shared__ char dynsm[];

__global__ __launch_bounds__(256, 1) void mma_gemm(
    int mode,
    const float* __restrict__ bias0, const float* __restrict__ bias1,
    const float* __restrict__ vm, const float* __restrict__ tm,
    float* __restrict__ out)
{
    const int z   = blockIdx.z;
    const int n0  = blockIdx.x * 128;
    const int m0  = blockIdx.y * 128;
    const int tid = threadIdx.x;

    const __nv_bfloat16 *Ahp, *Alp, *Bhp, *Blp;
    float* C = nullptr;
    const float* bias = z ? bias1 : bias0;
    const float* gate = nullptr;
    const float* mk   = nullptr;
    if (mode == 0) {
        Ahp = g_ah[z]; Alp = g_al[z]; Bhp = g_wk_h[z]; Blp = g_wk_l[z];
        gate = g_gate[z]; mk = z ? tm : vm;
    } else {
        Ahp = g_ph[z]; Alp = g_pl[z]; Bhp = g_wo_h[z]; Blp = g_wo_l[z];
        C = out + (size_t)z * Mtot * Dm;
    }

    const u32 sb = s2u(dynsm);
    const int wid = tid >> 5, lane = tid & 31;
    const int wm = (wid >> 2) * 64;
    const int wn = (wid & 3) * 32;
    const int grp = lane >> 3, lr = lane & 7;
    const int a_row = ((grp & 1) << 3) + lr;
    const int a_cb  = grp >> 1;
    const int b_row = ((grp & 2) << 2) + lr;
    const int b_cb  = grp & 1;

    const int r  = tid >> 1;
    const int c0 = (tid & 1) * 4;
    const __nv_bfloat16* gAh = Ahp + (size_t)(m0 + r) * Dm;
    const __nv_bfloat16* gAl = Alp + (size_t)(m0 + r) * Dm;
    const __nv_bfloat16* gBh = Bhp + (size_t)(n0 + r) * Dm;
    const __nv_bfloat16* gBl = Blp + (size_t)(n0 + r) * Dm;

    float acc[4][4][4];
#pragma unroll
    for (int i = 0; i < 4; i++)
#pragma unroll
        for (int j = 0; j < 4; j++)
#pragma unroll
            for (int q = 0; q < 4; q++) acc[i][j][q] = 0.f;

    auto load_stage = [&](int c, int buf) {
        const u32 st = sb + buf * 65536;
        const int ko = c * 64;
#pragma unroll
        for (int j = 0; j < 4; j++) {
            const u32 so = SWZ((u32)(r * 128 + (c0 + j) * 16));
            cpa16(st + so,         gAh + ko + (c0 + j) * 8);
            cpa16(st + 16384 + so, gAl + ko + (c0 + j) * 8);
            cpa16(st + 32768 + so, gBh + ko + (c0 + j) * 8);
            cpa16(st + 49152 + so, gBl + ko + (c0 + j) * 8);
        }
    };

    load_stage(0, 0);
    cpa_commit();
    load_stage(1, 1);
    cpa_commit();

    for (int c = 0; c < 16; c++) {
        if (c < 15) cpa_wait1(); else cpa_wait0();
        __syncthreads();
        if (c + 2 < 16) {
            load_stage(c + 2, (c + 2) % 3);
            cpa_commit();
        }

        const u32 st = sb + (u32)(c % 3) * 65536;
#pragma unroll
        for (int ks = 0; ks < 4; ks++) {
            u32 ah[4][4], al[4][4], bh[2][4], bl[2][4];
#pragma unroll
            for (int mf = 0; mf < 4; mf++) {
                const u32 off = SWZ((u32)((wm + mf * 16 + a_row) * 128 + (ks * 2 + a_cb) * 16));
                ldsm4(ah[mf][0], ah[mf][1], ah[mf][2], ah[mf][3], st + off);
                ldsm4(al[mf][0], al[mf][1], al[mf][2], al[mf][3], st + 16384 + off);
            }
#pragma unroll
            for (int np = 0; np < 2; np++) {
                const u32 off = SWZ((u32)((wn + np * 16 + b_row) * 128 + (ks * 2 + b_cb) * 16));
                ldsm4(bh[np][0], bh[np][1], bh[np][2], bh[np][3], st + 32768 + off);
                ldsm4(bl[np][0], bl[np][1], bl[np][2], bl[np][3], st + 49152 + off);
            }
#pragma unroll
            for (int mf = 0; mf < 4; mf++) {
#pragma unroll
                for (int nf = 0; nf < 4; nf++) {
                    const u32 bh0 = bh[nf >> 1][(nf & 1) * 2];
                    const u32 bh1 = bh[nf >> 1][(nf & 1) * 2 + 1];
                    const u32 bl0 = bl[nf >> 1][(nf & 1) * 2];
                    const u32 bl1 = bl[nf >> 1][(nf & 1) * 2 + 1];
                    mma16816(acc[mf][nf], ah[mf], bh0, bh1);
                    mma16816(acc[mf][nf], ah[mf], bl0, bl1);
                    mma16816(acc[mf][nf], al[mf], bh0, bh1);
                }
            }
        }
    }

    // ---- epilogue (R9 fragment-direct) ----
    const int batch = m0 >> 9;
    float bC[4][2], gC[4][2];
#pragma unroll
    for (int nf = 0; nf < 4; nf++) {
#pragma unroll
        for (int q = 0; q < 2; q++) {
            const int cc = n0 + wn + nf * 8 + (lane & 3) * 2 + q;
            bC[nf][q] = bias[cc];
            float g = 1.f;
            if (mode == 0 && cc < 2 * Dm) {
                g = 1.0f + gate[batch * Dm + (cc & (Dm - 1))];
                if (cc >= Dm) g *= 0.125f;
            }
            gC[nf][q] = g;
        }
    }

    if (mode == 0) {
        __nv_bfloat16* dH[3] = { g_kh[z], g_qh[z], g_vh[z] };
        __nv_bfloat16* dL[3] = { g_kl[z], g_ql[z], g_vl[z] };
#pragma unroll
        for (int mf = 0; mf < 4; mf++) {
            const int row0 = m0 + wm + mf * 16 + (lane >> 2);
            const int row1 = row0 + 8;
            const float mk0 = mk[batch * Nseq + (row0 & (Nseq - 1))];
            const float mk1 = mk[batch * Nseq + (row1 & (Nseq - 1))];
            const int tok0 = row0 & (Nseq - 1), tok1 = row1 & (Nseq - 1);
#pragma unroll
            for (int nf = 0; nf < 4; nf++) {
                const int col = n0 + wn + nf * 8 + (lane & 3) * 2;
                const int sec = col >> 10;
                const int d   = col & (Dm - 1);
                const int hh  = d >> 6;
                const int dh  = d & 63;
                float v00 = (acc[mf][nf][0] + bC[nf][0]) * mk0 * gC[nf][0];
                float v01 = (acc[mf][nf][1] + bC[nf][1]) * mk0 * gC[nf][1];
                float v10 = (acc[mf][nf][2] + bC[nf][0]) * mk1 * gC[nf][0];
                float v11 = (acc[mf][nf][3] + bC[nf][1]) * mk1 * gC[nf][1];
                u32 h0p, l0p, h1p, l1p;
                split_pair(v00, v01, h0p, l0p);
                split_pair(v10, v11, h1p, l1p);
                const size_t base = (size_t)(batch * Hh + hh) * Nseq;
                const size_t o0 = (base + tok0) * DHd + dh;
                const size_t o1 = (base + tok1) * DHd + dh;
                *reinterpret_cast<u32*>(dH[sec] + o0) = h0p;
                *reinterpret_cast<u32*>(dL[sec] + o0) = l0p;
                *reinterpret_cast<u32*>(dH[sec] + o1) = h1p;
                *reinterpret_cast<u32*>(dL[sec] + o1) = l1p;
            }
        }
    } else {
#pragma unroll
        for (int mf = 0; mf < 4; mf++) {
            const int row0 = m0 + wm + mf * 16 + (lane >> 2);
            const int row1 = row0 + 8;
#pragma unroll
            for (int nf = 0; nf < 4; nf++) {
                const int col = n0 + wn + nf * 8 + (lane & 3) * 2;
                float2 r0, r1;
                r0.x = acc[mf][nf][0] + bC[nf][0];
                r0.y = acc[mf][nf][1] + bC[nf][1];
                r1.x = acc[mf][nf][2] + bC[nf][0];
                r1.y = acc[mf][nf][3] + bC[nf][1];
                *reinterpret_cast<float2*>(C + (size_t)row0 * Dm + col) = r0;
                *reinterpret_cast<float2*>(C + (size_t)row1 * Dm + col) = r1;
            }
        }
    }
}

// ---------------------------------------------------------------------------
// Tensor-core flash attention (exact R9 version). CTA = 128 q-rows of one
// (z,b,h). 8 warps x 16 q-rows. Q frags register-resident; K/V cp.async
// double-buffered; online softmax in registers; FA2 S->P A-frag reuse.
// 3-term splits: QhKh+QhKl+QlKh ; PhVh+PlVh+PhVl. Writes g_upd.
// grid (Nseq/128=4, Hh, Bz*2), block 256. dyn smem = 100352 B.
// ---------------------------------------------------------------------------
#define ATTN_SMEM 100352

__global__ __launch_bounds__(256, 1) void attn_mma(
    const float* __restrict__ vm, const float* __restrict__ tm)
{
    const int b = blockIdx.z & (Bz - 1);
    const int z = blockIdx.z >> 5;
    const int h = blockIdx.y;
    const int q0 = blockIdx.x * 128;
    const int bh = b * Hh + h;
    const float* mk = z ? tm : vm;

    const __nv_bfloat16* Qh  = g_qh[z]  + (size_t)bh * Nseq * DHd;
    const __nv_bfloat16* Ql  = g_ql[z]  + (size_t)bh * Nseq * DHd;
    const __nv_bfloat16* Kh  = g_kh[z]  + (size_t)bh * Nseq * DHd;
    const __nv_bfloat16* Kl  = g_kl[z]  + (size_t)bh * Nseq * DHd;
    const __nv_bfloat16* Vth = g_vth[z] + (size_t)bh * DHd * Nseq;
    const __nv_bfloat16* Vtl = g_vtl[z] + (size_t)bh * DHd * Nseq;
    float* upd = z ? g_upd_t : g_upd_v;

    const u32 sb  = s2u(dynsm);
    const u32 sQh = sb;                  // 16KB
    const u32 sQl = sb + 16384;          // 16KB
    const u32 sK  = sb + 32768;          // 2 buf x (hi 8KB + lo 8KB) = 32KB
    const u32 sV  = sb + 65536;          // 32KB
    float* s_m = reinterpret_cast<float*>(dynsm + 98304);

    const int tid = threadIdx.x;
    const int wid = tid >> 5, lane = tid & 31;
    const int R = wid * 16;

    {
        const int r  = tid >> 1;
        const int e0 = (tid & 1) * 32;
#pragma unroll
        for (int i = 0; i < 4; i++) {
            const u32 so = SWZ((u32)(r * 128 + (e0 + i * 8) * 2));
            cpa16(sQh + so, Qh + (size_t)(q0 + r) * DHd + e0 + i * 8);
            cpa16(sQl + so, Ql + (size_t)(q0 + r) * DHd + e0 + i * 8);
        }
    }
    s_m[tid]       = mk[b * Nseq + tid];
    s_m[tid + 256] = mk[b * Nseq + tid + 256];
    {
        const int r  = tid >> 2;
        const int e0 = (tid & 3) * 16;
#pragma unroll
        for (int i = 0; i < 2; i++) {
            const u32 so = SWZ((u32)(r * 128 + (e0 + i * 8) * 2));
            cpa16(sK + so,        Kh  + (size_t)r * DHd + e0 + i * 8);
            cpa16(sK + 8192 + so, Kl  + (size_t)r * DHd + e0 + i * 8);
            cpa16(sV + so,        Vth + (size_t)r * Nseq + e0 + i * 8);
            cpa16(sV + 8192 + so, Vtl + (size_t)r * Nseq + e0 + i * 8);
        }
    }
    cpa_commit();
    cpa_wait0();
    __syncthreads();

    u32 qfh[4][4], qfl[4][4];
    {
        const int grp = lane >> 3, lr = lane & 7;
        const int a_row = ((grp & 1) << 3) + lr;
        const int a_cb  = grp >> 1;
#pragma unroll
        for (int kc = 0; kc < 4; kc++) {
            const u32 off = SWZ((u32)((R + a_row) * 128 + (kc * 2 + a_cb) * 16));
            ldsm4(qfh[kc][0], qfh[kc][1], qfh[kc][2], qfh[kc][3], sQh + off);
            ldsm4(qfl[kc][0], qfl[kc][1], qfl[kc][2], qfl[kc][3], sQl + off);
        }
    }

    const int grp = lane >> 3, lr = lane & 7;
    const int b_row = ((grp & 2) << 2) + lr;
    const int b_cb  = grp & 1;

    float m0r = -1e30f, m1r = -1e30f, l0r = 0.f, l1r = 0.f;
    float o[8][4];
#pragma unroll
    for (int nf = 0; nf < 8; nf++)
#pragma unroll
        for (int q = 0; q < 4; q++) o[nf][q] = 0.f;

    for (int st = 0; st < 8; st++) {
        const u32 buf = (u32)(st & 1) * 16384;
        if (st < 7) {
            const u32 nbuf = (u32)((st + 1) & 1) * 16384;
            const int kv = (st + 1) * 64;
            const int r  = tid >> 2;
            const int e0 = (tid & 3) * 16;
#pragma unroll
            for (int i = 0; i < 2; i++) {
                const u32 so = SWZ((u32)(r * 128 + (e0 + i * 8) * 2));
                cpa16(sK + nbuf + so,        Kh  + (size_t)(kv + r) * DHd + e0 + i * 8);
                cpa16(sK + nbuf + 8192 + so, Kl  + (size_t)(kv + r) * DHd + e0 + i * 8);
                cpa16(sV + nbuf + so,        Vth + (size_t)r * Nseq + kv + e0 + i * 8);
                cpa16(sV + nbuf + 8192 + so, Vtl + (size_t)r * Nseq + kv + e0 + i * 8);
            }
            cpa_commit();
            cpa_wait1();
        } else {
            cpa_wait0();
        }
        __syncthreads();

        float s[8][4];
#pragma unroll
        for (int nf = 0; nf < 8; nf++)
#pragma unroll
            for (int q = 0; q < 4; q++) s[nf][q] = 0.f;

        const u32 kb = sK + buf;
#pragma unroll
        for (int kc = 0; kc < 4; kc++) {
            u32 kh[4][4], kl[4][4];
#pragma unroll
            for (int np = 0; np < 4; np++) {
                const u32 off = SWZ((u32)((np * 16 + b_row) * 128 + (kc * 2 + b_cb) * 16));
                ldsm4(kh[np][0], kh[np][1], kh[np][2], kh[np][3], kb + off);
                ldsm4(kl[np][0], kl[np][1], kl[np][2], kl[np][3], kb + 8192 + off);
            }
#pragma unroll
            for (int np = 0; np < 4; np++) {
                mma16816(s[2 * np],     qfh[kc], kh[np][0], kh[np][1]);
                mma16816(s[2 * np],     qfh[kc], kl[np][0], kl[np][1]);
                mma16816(s[2 * np],     qfl[kc], kh[np][0], kh[np][1]);
                mma16816(s[2 * np + 1], qfh[kc], kh[np][2], kh[np][3]);
                mma16816(s[2 * np + 1], qfh[kc], kl[np][2], kl[np][3]);
                mma16816(s[2 * np + 1], qfl[kc], kh[np][2], kh[np][3]);
            }
        }

        const int cb0 = st * 64 + (lane & 3) * 2;
#pragma unroll
        for (int nf = 0; nf < 8; nf++) {
            if (s_m[cb0 + nf * 8] == 0.f)     { s[nf][0] = -1e30f; s[nf][2] = -1e30f; }
            if (s_m[cb0 + nf * 8 + 1] == 0.f) { s[nf][1] = -1e30f; s[nf][3] = -1e30f; }
        }

        float mx0 = -1e30f, mx1 = -1e30f;
#pragma unroll
        for (int nf = 0; nf < 8; nf++) {
            mx0 = fmaxf(mx0, fmaxf(s[nf][0], s[nf][1]));
            mx1 = fmaxf(mx1, fmaxf(s[nf][2], s[nf][3]));
        }
        mx0 = fmaxf(mx0, __shfl_xor_sync(0xffffffffu, mx0, 1));
        mx0 = fmaxf(mx0, __shfl_xor_sync(0xffffffffu, mx0, 2));
        mx1 = fmaxf(mx1, __shfl_xor_sync(0xffffffffu, mx1, 1));
        mx1 = fmaxf(mx1, __shfl_xor_sync(0xffffffffu, mx1, 2));

        const float nm0 = fmaxf(m0r, mx0), nm1 = fmaxf(m1r, mx1);
        const float c0 = fexp(m0r - nm0), c1 = fexp(m1r - nm1);

        float ps0 = 0.f, ps1 = 0.f;
#pragma unroll
        for (int nf = 0; nf < 8; nf++) {
            s[nf][0] = fexp(s[nf][0] - nm0); ps0 += s[nf][0];
            s[nf][1] = fexp(s[nf][1] - nm0); ps0 += s[nf][1];
            s[nf][2] = fexp(s[nf][2] - nm1); ps1 += s[nf][2];
            s[nf][3] = fexp(s[nf][3] - nm1); ps1 += s[nf][3];
        }
        ps0 += __shfl_xor_sync(0xffffffffu, ps0, 1);
        ps0 += __shfl_xor_sync(0xffffffffu, ps0, 2);
        ps1 += __shfl_xor_sync(0xffffffffu, ps1, 1);
        ps1 += __shfl_xor_sync(0xffffffffu, ps1, 2);

        l0r = l0r * c0 + ps0; m0r = nm0;
        l1r = l1r * c1 + ps1; m1r = nm1;
#pragma unroll
        for (int nf = 0; nf < 8; nf++) {
            o[nf][0] *= c0; o[nf][1] *= c0;
            o[nf][2] *= c1; o[nf][3] *= c1;
        }

        const u32 vb = sV + buf;
#pragma unroll
        for (int kc = 0; kc < 4; kc++) {
            u32 pah[4], pal[4];
            split_pair(s[2 * kc][0],     s[2 * kc][1],     pah[0], pal[0]);
            split_pair(s[2 * kc][2],     s[2 * kc][3],     pah[1], pal[1]);
            split_pair(s[2 * kc + 1][0], s[2 * kc + 1][1], pah[2], pal[2]);
            split_pair(s[2 * kc + 1][2], s[2 * kc + 1][3], pah[3], pal[3]);
#pragma unroll
            for (int np = 0; np < 4; np++) {
                const u32 off = SWZ((u32)((np * 16 + b_row) * 128 + (kc * 2 + b_cb) * 16));
                u32 vh0, vh1, vh2, vh3, vl0, vl1, vl2, vl3;
                ldsm4(vh0, vh1, vh2, vh3, vb + off);
                ldsm4(vl0, vl1, vl2, vl3, vb + 8192 + off);
                mma16816(o[2 * np],     pah, vh0, vh1);
                mma16816(o[2 * np],     pal, vh0, vh1);
                mma16816(o[2 * np],     pah, vl0, vl1);
                mma16816(o[2 * np + 1], pah, vh2, vh3);
                mma16816(o[2 * np + 1], pal, vh2, vh3);
                mma16816(o[2 * np + 1], pah, vl2, vl3);
            }
        }
        __syncthreads();
    }

    const float inv0 = 1.0f / l0r;
    const float inv1 = 1.0f / l1r;
    const int row0 = q0 + R + (lane >> 2);
    const int row1 = row0 + 8;
#pragma unroll
    for (int nf = 0; nf < 8; nf++) {
        const int d0 = nf * 8 + (lane & 3) * 2;
        float2 w0 = make_float2(o[nf][0] * inv0, o[nf][1] * inv0);
        float2 w1 = make_float2(o[nf][2] * inv1, o[nf][3] * inv1);
        *reinterpret_cast<float2*>(upd + (size_t)(b * Nseq + row0) * Dm + h * DHd + d0) = w0;
        *reinterpret_cast<float2*>(upd + (size_t)(b * Nseq + row1) * Dm + h * DHd + d0) = w1;
    }
}

// ---------------------------------------------------------------------------
// Launch (mma_gemm mode 0 is the 4th launch -> it gets ncu-profiled)
// ---------------------------------------------------------------------------
extern "C" void kernel_launch(void* const* d_in, const int* in_sizes, int n_in,
                              void* d_out, int out_size)
{
    const float* v     = (const float*)d_in[0];
    const float* t     = (const float*)d_in[1];
    const float* vm    = (const float*)d_in[2];
    const float* tm    = (const float*)d_in[3];
    const float* W_v4t = (const float*)d_in[4];
    const float* b_v4t = (const float*)d_in[5];
    const float* W_t4v = (const float*)d_in[6];
    const float* b_t4v = (const float*)d_in[7];
    const float* W_v   = (const float*)d_in[8];
    const float* b_v   = (const float*)d_in[9];
    const float* W_t   = (const float*)d_in[10];
    const float* b_t   = (const float*)d_in[11];
    const float* W_vo  = (const float*)d_in[12];
    const float* b_vo  = (const float*)d_in[13];
    const float* W_to  = (const float*)d_in[14];
    const float* b_to  = (const float*)d_in[15];
    float* out = (float*)d_out;

    cudaFuncSetAttribute(mma_gemm, cudaFuncAttributeMaxDynamicSharedMemorySize, SMEM_MMA);
    cudaFuncSetAttribute(attn_mma, cudaFuncAttributeMaxDynamicSharedMemorySize, ATTN_SMEM);

    meangate_kernel<<<dim3(Bz, 2), 256>>>(v, t, vm, tm, W_v4t, b_v4t, W_t4v, b_t4v);   // 1
    conv_wt<<<dim3(96, 32, 4), dim3(32, 8)>>>(W_v, W_t, W_vo, W_to);                    // 2
    conv_a_kqv<<<dim3(Mtot * Dm / 2048, 2), 256>>>(v, t);                               // 3

    mma_gemm<<<dim3(NT3 / 128, Mtot / 128, 2), 256, SMEM_MMA>>>(                        // 4 (profiled)
        0, b_v, b_t, vm, tm, out);

    vt_kernel<<<dim3(Nseq / 64, NBH, 2), 256>>>();                                      // 5

    attn_mma<<<dim3(Nseq / 128, Hh, Bz * 2), 256, ATTN_SMEM>>>(vm, tm);                 // 6

    conv_a_proj<<<dim3(Mtot * Dm / 2048, 2), 256>>>(v, t);                              // 7

    mma_gemm<<<dim3(Dm / 128, Mtot / 128, 2), 256, SMEM_MMA>>>(                         // 8
        1, b_vo, b_to, vm, tm, out);
}

// round 13
// speedup vs baseline: 1.4531x; 1.4531x over previous
#include <cuda_runtime.h>
#include <cuda_bf16.h>
#include <cstdint>

// Problem constants
#define Bz   32
#define Nseq 512
#define Dm   1024
#define Hh   16
#define DHd  64
#define Mtot (Bz * Nseq)          // 16384
#define NT3  (3 * Dm)             // 3072

typedef unsigned long long u64;
typedef unsigned int u32;

// ---------------------------------------------------------------------------
// Scratch (allocation-free rule: __device__ globals)
// ---------------------------------------------------------------------------
__device__ float g_gate[2][Bz * Dm];
__device__ float g_upd_v[Mtot * Dm];
__device__ float g_upd_t[Mtot * Dm];

// bf16-split operands for tensor-core GEMMs
__device__ __nv_bfloat16 g_ah[2][Mtot * Dm];   // relu(x) hi   (kqv A)
__device__ __nv_bfloat16 g_al[2][Mtot * Dm];   // relu(x) lo
__device__ __nv_bfloat16 g_ph[2][Mtot * Dm];   // (x+upd) hi   (proj A)
__device__ __nv_bfloat16 g_pl[2][Mtot * Dm];   // (x+upd) lo
__device__ __nv_bfloat16 g_wk_h[2][NT3 * Dm];  // W_v / W_t transposed [n][k] hi
__device__ __nv_bfloat16 g_wk_l[2][NT3 * Dm];
__device__ __nv_bfloat16 g_wo_h[2][Dm * Dm];   // W_vo / W_to transposed [n][k] hi
__device__ __nv_bfloat16 g_wo_l[2][Dm * Dm];

// Attention operands, per-head layout [bh][tok][64] (gated/masked, bf16 split)
#define NBH (Bz * Hh)
__device__ __nv_bfloat16 g_qh[2][NBH * Nseq * DHd];
__device__ __nv_bfloat16 g_ql[2][NBH * Nseq * DHd];
__device__ __nv_bfloat16 g_kh[2][NBH * Nseq * DHd];
__device__ __nv_bfloat16 g_kl[2][NBH * Nseq * DHd];
__device__ __nv_bfloat16 g_vh[2][NBH * Nseq * DHd];
__device__ __nv_bfloat16 g_vl[2][NBH * Nseq * DHd];
// V transposed per head: [bh][dh][tok]
__device__ __nv_bfloat16 g_vth[2][NBH * DHd * Nseq];
__device__ __nv_bfloat16 g_vtl[2][NBH * DHd * Nseq];

// ---------------------------------------------------------------------------
// Small helpers
// ---------------------------------------------------------------------------
__device__ __forceinline__ float fexp(float x) {
    x = fmaxf(x, -80.0f);
    float z  = fmaf(x, 1.4426950408889634f, 12582912.0f);
    int   ni = __float_as_int(z) - 0x4B400000;
    float nf = (float)ni;
    float r  = fmaf(nf, -0.693359375f, x);
    r        = fmaf(nf, 2.12194440e-4f, r);
    float p  = 1.9875691500e-4f;
    p = fmaf(p, r, 1.3981999507e-3f);
    p = fmaf(p, r, 8.3334519073e-3f);
    p = fmaf(p, r, 4.1665795894e-2f);
    p = fmaf(p, r, 1.6666665459e-1f);
    p = fmaf(p, r, 5.0000001201e-1f);
    float e = fmaf(r * r, p, r) + 1.0f;
    return __int_as_float(__float_as_int(e) + (ni << 23));
}

__device__ __forceinline__ void bsplit(float a, unsigned short& h, unsigned short& l) {
    __nv_bfloat16 hb = __float2bfloat16_rn(a);
    float lo = a - __bfloat162float(hb);
    __nv_bfloat16 lb = __float2bfloat16_rn(lo);
    h = __bfloat16_as_ushort(hb);
    l = __bfloat16_as_ushort(lb);
}
__device__ __forceinline__ u32 pkbf(unsigned short a, unsigned short b) {
    return ((u32)b << 16) | (u32)a;
}
__device__ __forceinline__ void split_pair(float x, float y, u32& hp, u32& lp) {
    unsigned short hx, lx, hy, ly;
    bsplit(x, hx, lx);
    bsplit(y, hy, ly);
    hp = pkbf(hx, hy);
    lp = pkbf(lx, ly);
}

__device__ __forceinline__ u32 s2u(const void* p) {
    u32 a; asm("{ .reg .u64 t; cvta.to.shared.u64 t,%1; cvt.u32.u64 %0,t; }" : "=r"(a) : "l"(p));
    return a;
}
#define SWZ(o) ((o) ^ (((o) >> 3) & 0x70))

// mma.sync / ldmatrix / cp.async wrappers (base-arch features)
__device__ __forceinline__ void ldsm4(u32& r0, u32& r1, u32& r2, u32& r3, u32 addr) {
    asm volatile("ldmatrix.sync.aligned.m8n8.x4.shared.b16 {%0,%1,%2,%3}, [%4];"
                 : "=r"(r0), "=r"(r1), "=r"(r2), "=r"(r3) : "r"(addr));
}
__device__ __forceinline__ void mma16816(float* d, const u32* a, u32 b0, u32 b1) {
    asm volatile(
        "mma.sync.aligned.m16n8k16.row.col.f32.bf16.bf16.f32 "
        "{%0,%1,%2,%3},{%4,%5,%6,%7},{%8,%9},{%0,%1,%2,%3};"
        : "+f"(d[0]), "+f"(d[1]), "+f"(d[2]), "+f"(d[3])
        : "r"(a[0]), "r"(a[1]), "r"(a[2]), "r"(a[3]), "r"(b0), "r"(b1));
}
__device__ __forceinline__ void cpa16(u32 saddr, const void* g) {
    asm volatile("cp.async.cg.shared.global [%0], [%1], 16;" :: "r"(saddr), "l"(g) : "memory");
}
__device__ __forceinline__ void cpa_commit() {
    asm volatile("cp.async.commit_group;" ::: "memory");
}
__device__ __forceinline__ void cpa_wait1() {
    asm volatile("cp.async.wait_group 1;" ::: "memory");
}
__device__ __forceinline__ void cpa_wait0() {
    asm volatile("cp.async.wait_group 0;" ::: "memory");
}

// ---------------------------------------------------------------------------
// Kernel 1: fused masked-mean + gate. grid (Bz, 2), block 256.
// ---------------------------------------------------------------------------
__global__ __launch_bounds__(256) void meangate_kernel(
    const float* __restrict__ v, const float* __restrict__ t,
    const float* __restrict__ vm, const float* __restrict__ tm,
    const float* __restrict__ W_v4t, const float* __restrict__ b_v4t,
    const float* __restrict__ W_t4v, const float* __restrict__ b_t4v)
{
    const int zg = blockIdx.y;
    const int b  = blockIdx.x;
    const float* X    = (zg ^ 1) ? t  : v;
    const float* mk   = (zg ^ 1) ? tm : vm;
    const float* W    = zg ? W_v4t : W_t4v;
    const float* bias = zg ? b_v4t : b_t4v;

    __shared__ float s_mean[Dm];
    __shared__ float s_mk[Nseq];
    __shared__ float s_red[256];

    const int tid = threadIdx.x;
    float csum = 0.f;
    for (int n = tid; n < Nseq; n += 256) {
        float m = mk[b * Nseq + n];
        s_mk[n] = m;
        csum += m;
    }
    s_red[tid] = csum;
    __syncthreads();
    for (int s = 128; s > 0; s >>= 1) {
        if (tid < s) s_red[tid] += s_red[tid + s];
        __syncthreads();
    }
    const float inv = 1.0f / s_red[0];

    float4 acc = make_float4(0.f, 0.f, 0.f, 0.f);
    const float* Xb = X + (size_t)b * Nseq * Dm + tid * 4;
    for (int n = 0; n < Nseq; n++) {
        const float m = s_mk[n];
        float4 xv = *reinterpret_cast<const float4*>(Xb + (size_t)n * Dm);
        acc.x = fmaf(xv.x, m, acc.x); acc.y = fmaf(xv.y, m, acc.y);
        acc.z = fmaf(xv.z, m, acc.z); acc.w = fmaf(xv.w, m, acc.w);
    }
    s_mean[tid * 4 + 0] = fmaxf(acc.x * inv, 0.f);
    s_mean[tid * 4 + 1] = fmaxf(acc.y * inv, 0.f);
    s_mean[tid * 4 + 2] = fmaxf(acc.z * inv, 0.f);
    s_mean[tid * 4 + 3] = fmaxf(acc.w * inv, 0.f);
    __syncthreads();

    float a[4];
#pragma unroll
    for (int k = 0; k < 4; k++) a[k] = bias[k * 256 + tid];
    for (int i = 0; i < Dm; i++) {
        const float sm = s_mean[i];
        const float* Wr = W + (size_t)i * Dm + tid;
#pragma unroll
        for (int k = 0; k < 4; k++)
            a[k] = fmaf(sm, Wr[k * 256], a[k]);
    }
#pragma unroll
    for (int k = 0; k < 4; k++) {
        float s = 1.0f / (1.0f + fexp(-fabsf(a[k])));
        g_gate[zg][b * Dm + k * 256 + tid] = (a[k] >= 0.f) ? s : (1.0f - s);
    }
}

// ---------------------------------------------------------------------------
// Conversion kernels
// ---------------------------------------------------------------------------
__global__ __launch_bounds__(256) void conv_a_kqv(
    const float* __restrict__ v, const float* __restrict__ t)
{
    const int z = blockIdx.y;
    const float* X = z ? t : v;
    size_t i = ((size_t)blockIdx.x * 256 + threadIdx.x) * 8;
    float4 a0 = *reinterpret_cast<const float4*>(X + i);
    float4 a1 = *reinterpret_cast<const float4*>(X + i + 4);
    float f[8] = {fmaxf(a0.x,0.f), fmaxf(a0.y,0.f), fmaxf(a0.z,0.f), fmaxf(a0.w,0.f),
                  fmaxf(a1.x,0.f), fmaxf(a1.y,0.f), fmaxf(a1.z,0.f), fmaxf(a1.w,0.f)};
    unsigned short h[8], l[8];
#pragma unroll
    for (int q = 0; q < 8; q++) bsplit(f[q], h[q], l[q]);
    uint4 H = make_uint4(pkbf(h[0],h[1]), pkbf(h[2],h[3]), pkbf(h[4],h[5]), pkbf(h[6],h[7]));
    uint4 L = make_uint4(pkbf(l[0],l[1]), pkbf(l[2],l[3]), pkbf(l[4],l[5]), pkbf(l[6],l[7]));
    *reinterpret_cast<uint4*>(&g_ah[z][i]) = H;
    *reinterpret_cast<uint4*>(&g_al[z][i]) = L;
}

__global__ __launch_bounds__(256) void conv_a_proj(
    const float* __restrict__ v, const float* __restrict__ t)
{
    const int z = blockIdx.y;
    const float* X = z ? t : v;
    const float* U = z ? g_upd_t : g_upd_v;
    size_t i = ((size_t)blockIdx.x * 256 + threadIdx.x) * 8;
    float4 a0 = *reinterpret_cast<const float4*>(X + i);
    float4 a1 = *reinterpret_cast<const float4*>(X + i + 4);
    float4 u0 = *reinterpret_cast<const float4*>(U + i);
    float4 u1 = *reinterpret_cast<const float4*>(U + i + 4);
    float f[8] = {a0.x+u0.x, a0.y+u0.y, a0.z+u0.z, a0.w+u0.w,
                  a1.x+u1.x, a1.y+u1.y, a1.z+u1.z, a1.w+u1.w};
    unsigned short h[8], l[8];
#pragma unroll
    for (int q = 0; q < 8; q++) bsplit(f[q], h[q], l[q]);
    uint4 H = make_uint4(pkbf(h[0],h[1]), pkbf(h[2],h[3]), pkbf(h[4],h[5]), pkbf(h[6],h[7]));
    uint4 L = make_uint4(pkbf(l[0],l[1]), pkbf(l[2],l[3]), pkbf(l[4],l[5]), pkbf(l[6],l[7]));
    *reinterpret_cast<uint4*>(&g_ph[z][i]) = H;
    *reinterpret_cast<uint4*>(&g_pl[z][i]) = L;
}

// Weight transpose + split, both weight sets in one launch.
__global__ void conv_wt(const float* __restrict__ Wv, const float* __restrict__ Wt,
                        const float* __restrict__ Wvo, const float* __restrict__ Wto)
{
    const int mode = blockIdx.z >> 1;
    const int z    = blockIdx.z & 1;
    const int N = mode ? Dm : NT3;
    if (blockIdx.x * 32 >= (unsigned)N) return;
    const float* W = mode ? (z ? Wto : Wvo) : (z ? Wt : Wv);
    __nv_bfloat16* Th = mode ? g_wo_h[z] : g_wk_h[z];
    __nv_bfloat16* Tl = mode ? g_wo_l[z] : g_wk_l[z];

    __shared__ float s[32][33];
    const int n0 = blockIdx.x * 32;
    const int k0 = blockIdx.y * 32;
    const int tx = threadIdx.x, ty = threadIdx.y;
    for (int dy = ty; dy < 32; dy += 8)
        s[dy][tx] = W[(size_t)(k0 + dy) * N + n0 + tx];
    __syncthreads();
    for (int dy = ty; dy < 32; dy += 8) {
        float a = s[tx][dy];
        unsigned short h, l;
        bsplit(a, h, l);
        size_t o = (size_t)(n0 + dy) * Dm + k0 + tx;
        Th[o] = __ushort_as_bfloat16(h);
        Tl[o] = __ushort_as_bfloat16(l);
    }
}

// V transpose per head: [bh][tok][dh] -> [bh][dh][tok], 64-token tiles
__global__ __launch_bounds__(256) void vt_kernel()
{
    const int z   = blockIdx.z;
    const int bh  = blockIdx.y;
    const int kt0 = blockIdx.x * 64;
    __shared__ unsigned short s[64][68];
    const int tid = threadIdx.x;
#pragma unroll
    for (int hl = 0; hl < 2; hl++) {
        const __nv_bfloat16* in = (hl ? g_vl[z] : g_vh[z]) + (size_t)bh * Nseq * DHd;
        __nv_bfloat16* op       = (hl ? g_vtl[z] : g_vth[z]) + (size_t)bh * DHd * Nseq;
        const u32* in32 = reinterpret_cast<const u32*>(in);
        u32* out32 = reinterpret_cast<u32*>(op);
        if (hl) __syncthreads();
        for (int i = tid; i < 64 * 32; i += 256) {
            const int tok = i >> 5, dc = i & 31;
            *reinterpret_cast<u32*>(&s[tok][dc * 2]) = in32[(size_t)(kt0 + tok) * 32 + dc];
        }
        __syncthreads();
        for (int i = tid; i < 64 * 32; i += 256) {
            const int dh = i >> 5, t2 = i & 31;
            const u32 w = ((u32)s[2 * t2 + 1][dh] << 16) | (u32)s[2 * t2][dh];
            out32[(size_t)dh * (Nseq / 2) + (kt0 >> 1) + t2] = w;
        }
    }
}

// ---------------------------------------------------------------------------
// Tensor-core GEMM (mma.sync HMMA) — R10 variant (fastest per-launch profile):
// CTA 128x128, 8 warps (2m x 4n), warp 64x32, m16n8k16 bf16->fp32,
// 3-term split term-outermost, 2-stage cp.async pipeline (2 x 64KB),
// smem-staged coalesced epilogue.
// mode 0: kqv -> gated/masked bf16-split Q/K/V per-head; mode 1: proj -> fp32.
// grid (NT/128, 128, 2), block 256.
// ---------------------------------------------------------------------------
#define SMEM_MMA (2 * 65536)
extern __shared__ char dynsm[];

__global__ __launch_bounds__(256, 1) void mma_gemm(
    int mode,
    const float* __restrict__ bias0, const float* __restrict__ bias1,
    const float* __restrict__ vm, const float* __restrict__ tm,
    float* __restrict__ out)
{
    const int z   = blockIdx.z;
    const int n0  = blockIdx.x * 128;
    const int m0  = blockIdx.y * 128;
    const int tid = threadIdx.x;

    const __nv_bfloat16 *Ahp, *Alp, *Bhp, *Blp;
    float* C = nullptr;
    const float* bias = z ? bias1 : bias0;
    const float* gate = nullptr;
    const float* mk   = nullptr;
    if (mode == 0) {
        Ahp = g_ah[z]; Alp = g_al[z]; Bhp = g_wk_h[z]; Blp = g_wk_l[z];
        gate = g_gate[z]; mk = z ? tm : vm;
    } else {
        Ahp = g_ph[z]; Alp = g_pl[z]; Bhp = g_wo_h[z]; Blp = g_wo_l[z];
        C = out + (size_t)z * Mtot * Dm;
    }

    const u32 sb = s2u(dynsm);
    const int wid = tid >> 5, lane = tid & 31;
    const int wm = (wid >> 2) * 64;
    const int wn = (wid & 3) * 32;
    const int grp = lane >> 3, lr = lane & 7;
    const int a_row = ((grp & 1) << 3) + lr;
    const int a_cb  = grp >> 1;
    const int b_row = ((grp & 2) << 2) + lr;
    const int b_cb  = grp & 1;

    const int r  = tid >> 1;
    const int c0 = (tid & 1) * 4;
    const __nv_bfloat16* gAh = Ahp + (size_t)(m0 + r) * Dm;
    const __nv_bfloat16* gAl = Alp + (size_t)(m0 + r) * Dm;
    const __nv_bfloat16* gBh = Bhp + (size_t)(n0 + r) * Dm;
    const __nv_bfloat16* gBl = Blp + (size_t)(n0 + r) * Dm;

    float acc[4][4][4];
#pragma unroll
    for (int i = 0; i < 4; i++)
#pragma unroll
        for (int j = 0; j < 4; j++)
#pragma unroll
            for (int q = 0; q < 4; q++) acc[i][j][q] = 0.f;

    auto load_stage = [&](int c, int buf) {
        const u32 st = sb + buf * 65536;
        const int ko = c * 64;
#pragma unroll
        for (int j = 0; j < 4; j++) {
            const u32 so = SWZ((u32)(r * 128 + (c0 + j) * 16));
            cpa16(st + so,         gAh + ko + (c0 + j) * 8);
            cpa16(st + 16384 + so, gAl + ko + (c0 + j) * 8);
            cpa16(st + 32768 + so, gBh + ko + (c0 + j) * 8);
            cpa16(st + 49152 + so, gBl + ko + (c0 + j) * 8);
        }
    };

    load_stage(0, 0);
    cpa_commit();

    for (int c = 0; c < 16; c++) {
        if (c + 1 < 16) {
            load_stage(c + 1, (c + 1) & 1);
            cpa_commit();
            cpa_wait1();
        } else {
            cpa_wait0();
        }
        __syncthreads();

        const u32 st = sb + (c & 1) * 65536;
#pragma unroll
        for (int ks = 0; ks < 4; ks++) {
            u32 ah[4][4], al[4][4], bh[2][4], bl[2][4];
#pragma unroll
            for (int mf = 0; mf < 4; mf++) {
                const u32 off = SWZ((u32)((wm + mf * 16 + a_row) * 128 + (ks * 2 + a_cb) * 16));
                ldsm4(ah[mf][0], ah[mf][1], ah[mf][2], ah[mf][3], st + off);
                ldsm4(al[mf][0], al[mf][1], al[mf][2], al[mf][3], st + 16384 + off);
            }
#pragma unroll
            for (int np = 0; np < 2; np++) {
                const u32 off = SWZ((u32)((wn + np * 16 + b_row) * 128 + (ks * 2 + b_cb) * 16));
                ldsm4(bh[np][0], bh[np][1], bh[np][2], bh[np][3], st + 32768 + off);
                ldsm4(bl[np][0], bl[np][1], bl[np][2], bl[np][3], st + 49152 + off);
            }
            // term-outermost: 16 independent accumulators between RAW reuses
#pragma unroll
            for (int term = 0; term < 3; term++) {
#pragma unroll
                for (int mf = 0; mf < 4; mf++) {
#pragma unroll
                    for (int nf = 0; nf < 4; nf++) {
                        const u32* aa = (term == 2) ? al[mf] : ah[mf];
                        const u32* bb = (term == 1) ? bl[nf >> 1] : bh[nf >> 1];
                        mma16816(acc[mf][nf], aa, bb[(nf & 1) * 2], bb[(nf & 1) * 2 + 1]);
                    }
                }
            }
        }
        __syncthreads();
    }

    // ---- epilogue: stage accumulators into smem, coalesced global stores ----
    float* se = reinterpret_cast<float*>(dynsm);
    const int SE_W = 132;
#pragma unroll
    for (int mf = 0; mf < 4; mf++) {
        const int r0 = wm + mf * 16 + (lane >> 2);
#pragma unroll
        for (int nf = 0; nf < 4; nf++) {
            const int cc = wn + nf * 8 + (lane & 3) * 2;
            *reinterpret_cast<float2*>(&se[r0 * SE_W + cc]) =
                make_float2(acc[mf][nf][0], acc[mf][nf][1]);
            *reinterpret_cast<float2*>(&se[(r0 + 8) * SE_W + cc]) =
                make_float2(acc[mf][nf][2], acc[mf][nf][3]);
        }
    }
    __syncthreads();

    const int batch = m0 >> 9;
    if (mode == 0) {
        __nv_bfloat16* dH[3] = { g_kh[z], g_qh[z], g_vh[z] };
        __nv_bfloat16* dL[3] = { g_kl[z], g_ql[z], g_vl[z] };
        const int sec  = n0 >> 10;      // whole CTA in one section (n-tile 128, sections 1024-aligned)
        const int nsec = n0 & 1023;
        __nv_bfloat16* DH = dH[sec];
        __nv_bfloat16* DL = dL[sec];
        for (int i = tid; i < 1024; i += 256) {
            const int tok = i >> 3;
            const int cc0 = (i & 7) * 16;
            const int tokg = (m0 + tok) & (Nseq - 1);
            const float mskv = mk[batch * Nseq + tokg];
            u32 hp[8], lp[8];
#pragma unroll
            for (int q = 0; q < 8; q++) {
                float f0 = mskv, f1 = mskv;
                const int cg0 = nsec + cc0 + 2 * q;
                if (sec < 2) {
                    f0 *= 1.0f + gate[batch * Dm + cg0];
                    f1 *= 1.0f + gate[batch * Dm + cg0 + 1];
                    if (sec == 1) { f0 *= 0.125f; f1 *= 0.125f; }
                }
                float v0 = (se[tok * SE_W + cc0 + 2 * q]     + bias[n0 + cc0 + 2 * q])     * f0;
                float v1 = (se[tok * SE_W + cc0 + 2 * q + 1] + bias[n0 + cc0 + 2 * q + 1]) * f1;
                split_pair(v0, v1, hp[q], lp[q]);
            }
            const int hh  = (nsec + cc0) >> 6;
            const int dh0 = (nsec + cc0) & 63;
            const size_t o = ((size_t)(batch * Hh + hh) * Nseq + tokg) * DHd + dh0;
            *reinterpret_cast<uint4*>(DH + o)     = make_uint4(hp[0], hp[1], hp[2], hp[3]);
            *reinterpret_cast<uint4*>(DH + o + 8) = make_uint4(hp[4], hp[5], hp[6], hp[7]);
            *reinterpret_cast<uint4*>(DL + o)     = make_uint4(lp[0], lp[1], lp[2], lp[3]);
            *reinterpret_cast<uint4*>(DL + o + 8) = make_uint4(lp[4], lp[5], lp[6], lp[7]);
        }
    } else {
        for (int i = tid; i < 1024; i += 256) {
            const int tok = i >> 3;
            const int cc0 = (i & 7) * 16;
            float* dst = C + (size_t)(m0 + tok) * Dm + n0 + cc0;
#pragma unroll
            for (int q = 0; q < 4; q++) {
                float4 w;
                w.x = se[tok * SE_W + cc0 + q * 4 + 0] + bias[n0 + cc0 + q * 4 + 0];
                w.y = se[tok * SE_W + cc0 + q * 4 + 1] + bias[n0 + cc0 + q * 4 + 1];
                w.z = se[tok * SE_W + cc0 + q * 4 + 2] + bias[n0 + cc0 + q * 4 + 2];
                w.w = se[tok * SE_W + cc0 + q * 4 + 3] + bias[n0 + cc0 + q * 4 + 3];
                *reinterpret_cast<float4*>(dst + q * 4) = w;
            }
        }
    }
}

// ---------------------------------------------------------------------------
// Tensor-core flash attention (exact R9 version, the measured best).
// CTA = 128 q-rows of one (z,b,h). 8 warps x 16 q-rows. Q frags register-
// resident; K/V cp.async double-buffered; online softmax in registers;
// FA2 S->P A-frag reuse. 3-term splits. Writes g_upd.
// grid (Nseq/128=4, Hh, Bz*2), block 256. dyn smem = 100352 B.
// ---------------------------------------------------------------------------
#define ATTN_SMEM 100352

__global__ __launch_bounds__(256, 1) void attn_mma(
    const float* __restrict__ vm, const float* __restrict__ tm)
{
    const int b = blockIdx.z & (Bz - 1);
    const int z = blockIdx.z >> 5;
    const int h = blockIdx.y;
    const int q0 = blockIdx.x * 128;
    const int bh = b * Hh + h;
    const float* mk = z ? tm : vm;

    const __nv_bfloat16* Qh  = g_qh[z]  + (size_t)bh * Nseq * DHd;
    const __nv_bfloat16* Ql  = g_ql[z]  + (size_t)bh * Nseq * DHd;
    const __nv_bfloat16* Kh  = g_kh[z]  + (size_t)bh * Nseq * DHd;
    const __nv_bfloat16* Kl  = g_kl[z]  + (size_t)bh * Nseq * DHd;
    const __nv_bfloat16* Vth = g_vth[z] + (size_t)bh * DHd * Nseq;
    const __nv_bfloat16* Vtl = g_vtl[z] + (size_t)bh * DHd * Nseq;
    float* upd = z ? g_upd_t : g_upd_v;

    const u32 sb  = s2u(dynsm);
    const u32 sQh = sb;                  // 16KB
    const u32 sQl = sb + 16384;          // 16KB
    const u32 sK  = sb + 32768;          // 2 buf x (hi 8KB + lo 8KB) = 32KB
    const u32 sV  = sb + 65536;          // 32KB
    float* s_m = reinterpret_cast<float*>(dynsm + 98304);

    const int tid = threadIdx.x;
    const int wid = tid >> 5, lane = tid & 31;
    const int R = wid * 16;

    {
        const int r  = tid >> 1;
        const int e0 = (tid & 1) * 32;
#pragma unroll
        for (int i = 0; i < 4; i++) {
            const u32 so = SWZ((u32)(r * 128 + (e0 + i * 8) * 2));
            cpa16(sQh + so, Qh + (size_t)(q0 + r) * DHd + e0 + i * 8);
            cpa16(sQl + so, Ql + (size_t)(q0 + r) * DHd + e0 + i * 8);
        }
    }
    s_m[tid]       = mk[b * Nseq + tid];
    s_m[tid + 256] = mk[b * Nseq + tid + 256];
    {
        const int r  = tid >> 2;
        const int e0 = (tid & 3) * 16;
#pragma unroll
        for (int i = 0; i < 2; i++) {
            const u32 so = SWZ((u32)(r * 128 + (e0 + i * 8) * 2));
            cpa16(sK + so,        Kh  + (size_t)r * DHd + e0 + i * 8);
            cpa16(sK + 8192 + so, Kl  + (size_t)r * DHd + e0 + i * 8);
            cpa16(sV + so,        Vth + (size_t)r * Nseq + e0 + i * 8);
            cpa16(sV + 8192 + so, Vtl + (size_t)r * Nseq + e0 + i * 8);
        }
    }
    cpa_commit();
    cpa_wait0();
    __syncthreads();

    u32 qfh[4][4], qfl[4][4];
    {
        const int grp = lane >> 3, lr = lane & 7;
        const int a_row = ((grp & 1) << 3) + lr;
        const int a_cb  = grp >> 1;
#pragma unroll
        for (int kc = 0; kc < 4; kc++) {
            const u32 off = SWZ((u32)((R + a_row) * 128 + (kc * 2 + a_cb) * 16));
            ldsm4(qfh[kc][0], qfh[kc][1], qfh[kc][2], qfh[kc][3], sQh + off);
            ldsm4(qfl[kc][0], qfl[kc][1], qfl[kc][2], qfl[kc][3], sQl + off);
        }
    }

    const int grp = lane >> 3, lr = lane & 7;
    const int b_row = ((grp & 2) << 2) + lr;
    const int b_cb  = grp & 1;

    float m0r = -1e30f, m1r = -1e30f, l0r = 0.f, l1r = 0.f;
    float o[8][4];
#pragma unroll
    for (int nf = 0; nf < 8; nf++)
#pragma unroll
        for (int q = 0; q < 4; q++) o[nf][q] = 0.f;

    for (int st = 0; st < 8; st++) {
        const u32 buf = (u32)(st & 1) * 16384;
        if (st < 7) {
            const u32 nbuf = (u32)((st + 1) & 1) * 16384;
            const int kv = (st + 1) * 64;
            const int r  = tid >> 2;
            const int e0 = (tid & 3) * 16;
#pragma unroll
            for (int i = 0; i < 2; i++) {
                const u32 so = SWZ((u32)(r * 128 + (e0 + i * 8) * 2));
                cpa16(sK + nbuf + so,        Kh  + (size_t)(kv + r) * DHd + e0 + i * 8);
                cpa16(sK + nbuf + 8192 + so, Kl  + (size_t)(kv + r) * DHd + e0 + i * 8);
                cpa16(sV + nbuf + so,        Vth + (size_t)r * Nseq + kv + e0 + i * 8);
                cpa16(sV + nbuf + 8192 + so, Vtl + (size_t)r * Nseq + kv + e0 + i * 8);
            }
            cpa_commit();
            cpa_wait1();
        } else {
            cpa_wait0();
        }
        __syncthreads();

        float s[8][4];
#pragma unroll
        for (int nf = 0; nf < 8; nf++)
#pragma unroll
            for (int q = 0; q < 4; q++) s[nf][q] = 0.f;

        const u32 kb = sK + buf;
#pragma unroll
        for (int kc = 0; kc < 4; kc++) {
            u32 kh[4][4], kl[4][4];
#pragma unroll
            for (int np = 0; np < 4; np++) {
                const u32 off = SWZ((u32)((np * 16 + b_row) * 128 + (kc * 2 + b_cb) * 16));
                ldsm4(kh[np][0], kh[np][1], kh[np][2], kh[np][3], kb + off);
                ldsm4(kl[np][0], kl[np][1], kl[np][2], kl[np][3], kb + 8192 + off);
            }
#pragma unroll
            for (int np = 0; np < 4; np++) {
                mma16816(s[2 * np],     qfh[kc], kh[np][0], kh[np][1]);
                mma16816(s[2 * np],     qfh[kc], kl[np][0], kl[np][1]);
                mma16816(s[2 * np],     qfl[kc], kh[np][0], kh[np][1]);
                mma16816(s[2 * np + 1], qfh[kc], kh[np][2], kh[np][3]);
                mma16816(s[2 * np + 1], qfh[kc], kl[np][2], kl[np][3]);
                mma16816(s[2 * np + 1], qfl[kc], kh[np][2], kh[np][3]);
            }
        }

        const int cb0 = st * 64 + (lane & 3) * 2;
#pragma unroll
        for (int nf = 0; nf < 8; nf++) {
            if (s_m[cb0 + nf * 8] == 0.f)     { s[nf][0] = -1e30f; s[nf][2] = -1e30f; }
            if (s_m[cb0 + nf * 8 + 1] == 0.f) { s[nf][1] = -1e30f; s[nf][3] = -1e30f; }
        }

        float mx0 = -1e30f, mx1 = -1e30f;
#pragma unroll
        for (int nf = 0; nf < 8; nf++) {
            mx0 = fmaxf(mx0, fmaxf(s[nf][0], s[nf][1]));
            mx1 = fmaxf(mx1, fmaxf(s[nf][2], s[nf][3]));
        }
        mx0 = fmaxf(mx0, __shfl_xor_sync(0xffffffffu, mx0, 1));
        mx0 = fmaxf(mx0, __shfl_xor_sync(0xffffffffu, mx0, 2));
        mx1 = fmaxf(mx1, __shfl_xor_sync(0xffffffffu, mx1, 1));
        mx1 = fmaxf(mx1, __shfl_xor_sync(0xffffffffu, mx1, 2));

        const float nm0 = fmaxf(m0r, mx0), nm1 = fmaxf(m1r, mx1);
        const float c0 = fexp(m0r - nm0), c1 = fexp(m1r - nm1);

        float ps0 = 0.f, ps1 = 0.f;
#pragma unroll
        for (int nf = 0; nf < 8; nf++) {
            s[nf][0] = fexp(s[nf][0] - nm0); ps0 += s[nf][0];
            s[nf][1] = fexp(s[nf][1] - nm0); ps0 += s[nf][1];
            s[nf][2] = fexp(s[nf][2] - nm1); ps1 += s[nf][2];
            s[nf][3] = fexp(s[nf][3] - nm1); ps1 += s[nf][3];
        }
        ps0 += __shfl_xor_sync(0xffffffffu, ps0, 1);
        ps0 += __shfl_xor_sync(0xffffffffu, ps0, 2);
        ps1 += __shfl_xor_sync(0xffffffffu, ps1, 1);
        ps1 += __shfl_xor_sync(0xffffffffu, ps1, 2);

        l0r = l0r * c0 + ps0; m0r = nm0;
        l1r = l1r * c1 + ps1; m1r = nm1;
#pragma unroll
        for (int nf = 0; nf < 8; nf++) {
            o[nf][0] *= c0; o[nf][1] *= c0;
            o[nf][2] *= c1; o[nf][3] *= c1;
        }

        const u32 vb = sV + buf;
#pragma unroll
        for (int kc = 0; kc < 4; kc++) {
            u32 pah[4], pal[4];
            split_pair(s[2 * kc][0],     s[2 * kc][1],     pah[0], pal[0]);
            split_pair(s[2 * kc][2],     s[2 * kc][3],     pah[1], pal[1]);
            split_pair(s[2 * kc + 1][0], s[2 * kc + 1][1], pah[2], pal[2]);
            split_pair(s[2 * kc + 1][2], s[2 * kc + 1][3], pah[3], pal[3]);
#pragma unroll
            for (int np = 0; np < 4; np++) {
                const u32 off = SWZ((u32)((np * 16 + b_row) * 128 + (kc * 2 + b_cb) * 16));
                u32 vh0, vh1, vh2, vh3, vl0, vl1, vl2, vl3;
                ldsm4(vh0, vh1, vh2, vh3, vb + off);
                ldsm4(vl0, vl1, vl2, vl3, vb + 8192 + off);
                mma16816(o[2 * np],     pah, vh0, vh1);
                mma16816(o[2 * np],     pal, vh0, vh1);
                mma16816(o[2 * np],     pah, vl0, vl1);
                mma16816(o[2 * np + 1], pah, vh2, vh3);
                mma16816(o[2 * np + 1], pal, vh2, vh3);
                mma16816(o[2 * np + 1], pah, vl2, vl3);
            }
        }
        __syncthreads();
    }

    const float inv0 = 1.0f / l0r;
    const float inv1 = 1.0f / l1r;
    const int row0 = q0 + R + (lane >> 2);
    const int row1 = row0 + 8;
#pragma unroll
    for (int nf = 0; nf < 8; nf++) {
        const int d0 = nf * 8 + (lane & 3) * 2;
        float2 w0 = make_float2(o[nf][0] * inv0, o[nf][1] * inv0);
        float2 w1 = make_float2(o[nf][2] * inv1, o[nf][3] * inv1);
        *reinterpret_cast<float2*>(upd + (size_t)(b * Nseq + row0) * Dm + h * DHd + d0) = w0;
        *reinterpret_cast<float2*>(upd + (size_t)(b * Nseq + row1) * Dm + h * DHd + d0) = w1;
    }
}

// ---------------------------------------------------------------------------
// Launch (mma_gemm mode 0 is the 4th launch -> it gets ncu-profiled)
// ---------------------------------------------------------------------------
extern "C" void kernel_launch(void* const* d_in, const int* in_sizes, int n_in,
                              void* d_out, int out_size)
{
    const float* v     = (const float*)d_in[0];
    const float* t     = (const float*)d_in[1];
    const float* vm    = (const float*)d_in[2];
    const float* tm    = (const float*)d_in[3];
    const float* W_v4t = (const float*)d_in[4];
    const float* b_v4t = (const float*)d_in[5];
    const float* W_t4v = (const float*)d_in[6];
    const float* b_t4v = (const float*)d_in[7];
    const float* W_v   = (const float*)d_in[8];
    const float* b_v   = (const float*)d_in[9];
    const float* W_t   = (const float*)d_in[10];
    const float* b_t   = (const float*)d_in[11];
    const float* W_vo  = (const float*)d_in[12];
    const float* b_vo  = (const float*)d_in[13];
    const float* W_to  = (const float*)d_in[14];
    const float* b_to  = (const float*)d_in[15];
    float* out = (float*)d_out;

    cudaFuncSetAttribute(mma_gemm, cudaFuncAttributeMaxDynamicSharedMemorySize, SMEM_MMA);
    cudaFuncSetAttribute(attn_mma, cudaFuncAttributeMaxDynamicSharedMemorySize, ATTN_SMEM);

    meangate_kernel<<<dim3(Bz, 2), 256>>>(v, t, vm, tm, W_v4t, b_v4t, W_t4v, b_t4v);   // 1
    conv_wt<<<dim3(96, 32, 4), dim3(32, 8)>>>(W_v, W_t, W_vo, W_to);                    // 2
    conv_a_kqv<<<dim3(Mtot * Dm / 2048, 2), 256>>>(v, t);                               // 3

    mma_gemm<<<dim3(NT3 / 128, Mtot / 128, 2), 256, SMEM_MMA>>>(                        // 4 (profiled)
        0, b_v, b_t, vm, tm, out);

    vt_kernel<<<dim3(Nseq / 64, NBH, 2), 256>>>();                                      // 5

    attn_mma<<<dim3(Nseq / 128, Hh, Bz * 2), 256, ATTN_SMEM>>>(vm, tm);                 // 6

    conv_a_proj<<<dim3(Mtot * Dm / 2048, 2), 256>>>(v, t);                              // 7

    mma_gemm<<<dim3(Dm / 128, Mtot / 128, 2), 256, SMEM_MMA>>>(                         // 8
        1, b_vo, b_to, vm, tm, out);
}

// round 14
// speedup vs baseline: 1.6297x; 1.1215x over previous
#include <cuda_runtime.h>
#include <cuda_bf16.h>
#include <cstdint>

// Problem constants
#define Bz   32
#define Nseq 512
#define Dm   1024
#define Hh   16
#define DHd  64
#define Mtot (Bz * Nseq)          // 16384
#define NT3  (3 * Dm)             // 3072

typedef unsigned long long u64;
typedef unsigned int u32;

// ---------------------------------------------------------------------------
// Scratch (allocation-free rule: __device__ globals)
// ---------------------------------------------------------------------------
__device__ float g_upd_v[Mtot * Dm];
__device__ float g_upd_t[Mtot * Dm];
__device__ float g_mean[2][Bz * Dm];
__device__ float g_gate[2][Bz * Dm];

// bf16-split operands for tensor-core GEMMs
__device__ __nv_bfloat16 g_ah[2][Mtot * Dm];   // relu(x) hi   (kqv A)
__device__ __nv_bfloat16 g_al[2][Mtot * Dm];   // relu(x) lo
__device__ __nv_bfloat16 g_ph[2][Mtot * Dm];   // (x+upd) hi   (proj A)
__device__ __nv_bfloat16 g_pl[2][Mtot * Dm];   // (x+upd) lo
__device__ __nv_bfloat16 g_wk_h[2][NT3 * Dm];  // W_v / W_t transposed [n][k] hi
__device__ __nv_bfloat16 g_wk_l[2][NT3 * Dm];
__device__ __nv_bfloat16 g_wo_h[2][Dm * Dm];   // W_vo / W_to transposed [n][k] hi
__device__ __nv_bfloat16 g_wo_l[2][Dm * Dm];

// Attention operands, per-head layout [bh][tok][64] (gated/masked, bf16 split)
#define NBH (Bz * Hh)
__device__ __nv_bfloat16 g_qh[2][NBH * Nseq * DHd];
__device__ __nv_bfloat16 g_ql[2][NBH * Nseq * DHd];
__device__ __nv_bfloat16 g_kh[2][NBH * Nseq * DHd];
__device__ __nv_bfloat16 g_kl[2][NBH * Nseq * DHd];
__device__ __nv_bfloat16 g_vh[2][NBH * Nseq * DHd];
__device__ __nv_bfloat16 g_vl[2][NBH * Nseq * DHd];
// V transposed per head: [bh][dh][tok]
__device__ __nv_bfloat16 g_vth[2][NBH * DHd * Nseq];
__device__ __nv_bfloat16 g_vtl[2][NBH * DHd * Nseq];

// ---------------------------------------------------------------------------
// Small helpers
// ---------------------------------------------------------------------------
__device__ __forceinline__ float fexp(float x) {
    x = fmaxf(x, -80.0f);
    float z  = fmaf(x, 1.4426950408889634f, 12582912.0f);
    int   ni = __float_as_int(z) - 0x4B400000;
    float nf = (float)ni;
    float r  = fmaf(nf, -0.693359375f, x);
    r        = fmaf(nf, 2.12194440e-4f, r);
    float p  = 1.9875691500e-4f;
    p = fmaf(p, r, 1.3981999507e-3f);
    p = fmaf(p, r, 8.3334519073e-3f);
    p = fmaf(p, r, 4.1665795894e-2f);
    p = fmaf(p, r, 1.6666665459e-1f);
    p = fmaf(p, r, 5.0000001201e-1f);
    float e = fmaf(r * r, p, r) + 1.0f;
    return __int_as_float(__float_as_int(e) + (ni << 23));
}

__device__ __forceinline__ void bsplit(float a, unsigned short& h, unsigned short& l) {
    __nv_bfloat16 hb = __float2bfloat16_rn(a);
    float lo = a - __bfloat162float(hb);
    __nv_bfloat16 lb = __float2bfloat16_rn(lo);
    h = __bfloat16_as_ushort(hb);
    l = __bfloat16_as_ushort(lb);
}
__device__ __forceinline__ u32 pkbf(unsigned short a, unsigned short b) {
    return ((u32)b << 16) | (u32)a;
}
__device__ __forceinline__ void split_pair(float x, float y, u32& hp, u32& lp) {
    unsigned short hx, lx, hy, ly;
    bsplit(x, hx, lx);
    bsplit(y, hy, ly);
    hp = pkbf(hx, hy);
    lp = pkbf(lx, ly);
}

__device__ __forceinline__ u32 s2u(const void* p) {
    u32 a; asm("{ .reg .u64 t; cvta.to.shared.u64 t,%1; cvt.u32.u64 %0,t; }" : "=r"(a) : "l"(p));
    return a;
}
#define SWZ(o) ((o) ^ (((o) >> 3) & 0x70))

// mma.sync / ldmatrix / cp.async wrappers (base-arch features)
__device__ __forceinline__ void ldsm4(u32& r0, u32& r1, u32& r2, u32& r3, u32 addr) {
    asm volatile("ldmatrix.sync.aligned.m8n8.x4.shared.b16 {%0,%1,%2,%3}, [%4];"
                 : "=r"(r0), "=r"(r1), "=r"(r2), "=r"(r3) : "r"(addr));
}
__device__ __forceinline__ void mma16816(float* d, const u32* a, u32 b0, u32 b1) {
    asm volatile(
        "mma.sync.aligned.m16n8k16.row.col.f32.bf16.bf16.f32 "
        "{%0,%1,%2,%3},{%4,%5,%6,%7},{%8,%9},{%0,%1,%2,%3};"
        : "+f"(d[0]), "+f"(d[1]), "+f"(d[2]), "+f"(d[3])
        : "r"(a[0]), "r"(a[1]), "r"(a[2]), "r"(a[3]), "r"(b0), "r"(b1));
}
__device__ __forceinline__ void cpa16(u32 saddr, const void* g) {
    asm volatile("cp.async.cg.shared.global [%0], [%1], 16;" :: "r"(saddr), "l"(g) : "memory");
}
__device__ __forceinline__ void cpa_commit() {
    asm volatile("cp.async.commit_group;" ::: "memory");
}
__device__ __forceinline__ void cpa_wait1() {
    asm volatile("cp.async.wait_group 1;" ::: "memory");
}
__device__ __forceinline__ void cpa_wait0() {
    asm volatile("cp.async.wait_group 0;" ::: "memory");
}

// ---------------------------------------------------------------------------
// Kernel 1: masked mean (R9 version)
// ---------------------------------------------------------------------------
__global__ __launch_bounds__(256) void mean_kernel(
    const float* __restrict__ v, const float* __restrict__ t,
    const float* __restrict__ vm, const float* __restrict__ tm)
{
    const int z = blockIdx.z;
    const int b = blockIdx.y;
    const float* X  = z ? t  : v;
    const float* mk = z ? tm : vm;

    __shared__ float s_mk[Nseq];
    __shared__ float s_red[256];

    const int tid = threadIdx.x;
    float c = 0.f;
    for (int n = tid; n < Nseq; n += 256) {
        float m = mk[b * Nseq + n];
        s_mk[n] = m;
        c += m;
    }
    s_red[tid] = c;
    __syncthreads();
    for (int s = 128; s > 0; s >>= 1) {
        if (tid < s) s_red[tid] += s_red[tid + s];
        __syncthreads();
    }
    const float inv = 1.0f / s_red[0];

    const int d = blockIdx.x * 256 + tid;
    float acc = 0.f;
    for (int n = 0; n < Nseq; n++)
        acc = fmaf(X[(size_t)(b * Nseq + n) * Dm + d], s_mk[n], acc);
    g_mean[z][b * Dm + d] = acc * inv;
}

// ---------------------------------------------------------------------------
// Kernel 2: gates (R9 version)
// ---------------------------------------------------------------------------
__global__ __launch_bounds__(128) void gate_kernel(
    const float* __restrict__ W_v4t, const float* __restrict__ b_v4t,
    const float* __restrict__ W_t4v, const float* __restrict__ b_t4v)
{
    const int z = blockIdx.z;
    const int b = blockIdx.y;
    const float* mean = g_mean[z ^ 1];
    const float* W    = z ? W_v4t : W_t4v;
    const float* bias = z ? b_v4t : b_t4v;

    __shared__ float s_m[Dm];
    const int tid = threadIdx.x;
    for (int i = tid; i < Dm; i += 128)
        s_m[i] = fmaxf(mean[b * Dm + i], 0.f);
    __syncthreads();

    const int j = blockIdx.x * 128 + tid;
    float acc = bias[j];
    for (int i = 0; i < Dm; i++)
        acc = fmaf(s_m[i], W[(size_t)i * Dm + j], acc);
    float s = 1.0f / (1.0f + fexp(-fabsf(acc)));
    g_gate[z][b * Dm + j] = (acc >= 0.f) ? s : (1.0f - s);
}

// ---------------------------------------------------------------------------
// Conversion kernels (R9 versions)
// ---------------------------------------------------------------------------
__global__ __launch_bounds__(256) void conv_a_kqv(
    const float* __restrict__ v, const float* __restrict__ t)
{
    const int z = blockIdx.y;
    const float* X = z ? t : v;
    size_t i = ((size_t)blockIdx.x * 256 + threadIdx.x) * 8;
    float4 a0 = *reinterpret_cast<const float4*>(X + i);
    float4 a1 = *reinterpret_cast<const float4*>(X + i + 4);
    float f[8] = {fmaxf(a0.x,0.f), fmaxf(a0.y,0.f), fmaxf(a0.z,0.f), fmaxf(a0.w,0.f),
                  fmaxf(a1.x,0.f), fmaxf(a1.y,0.f), fmaxf(a1.z,0.f), fmaxf(a1.w,0.f)};
    unsigned short h[8], l[8];
#pragma unroll
    for (int q = 0; q < 8; q++) bsplit(f[q], h[q], l[q]);
    uint4 H = make_uint4(pkbf(h[0],h[1]), pkbf(h[2],h[3]), pkbf(h[4],h[5]), pkbf(h[6],h[7]));
    uint4 L = make_uint4(pkbf(l[0],l[1]), pkbf(l[2],l[3]), pkbf(l[4],l[5]), pkbf(l[6],l[7]));
    *reinterpret_cast<uint4*>(&g_ah[z][i]) = H;
    *reinterpret_cast<uint4*>(&g_al[z][i]) = L;
}

__global__ __launch_bounds__(256) void conv_a_proj(
    const float* __restrict__ v, const float* __restrict__ t)
{
    const int z = blockIdx.y;
    const float* X = z ? t : v;
    const float* U = z ? g_upd_t : g_upd_v;
    size_t i = ((size_t)blockIdx.x * 256 + threadIdx.x) * 8;
    float4 a0 = *reinterpret_cast<const float4*>(X + i);
    float4 a1 = *reinterpret_cast<const float4*>(X + i + 4);
    float4 u0 = *reinterpret_cast<const float4*>(U + i);
    float4 u1 = *reinterpret_cast<const float4*>(U + i + 4);
    float f[8] = {a0.x+u0.x, a0.y+u0.y, a0.z+u0.z, a0.w+u0.w,
                  a1.x+u1.x, a1.y+u1.y, a1.z+u1.z, a1.w+u1.w};
    unsigned short h[8], l[8];
#pragma unroll
    for (int q = 0; q < 8; q++) bsplit(f[q], h[q], l[q]);
    uint4 H = make_uint4(pkbf(h[0],h[1]), pkbf(h[2],h[3]), pkbf(h[4],h[5]), pkbf(h[6],h[7]));
    uint4 L = make_uint4(pkbf(l[0],l[1]), pkbf(l[2],l[3]), pkbf(l[4],l[5]), pkbf(l[6],l[7]));
    *reinterpret_cast<uint4*>(&g_ph[z][i]) = H;
    *reinterpret_cast<uint4*>(&g_pl[z][i]) = L;
}

// Weight transpose + split: W [1024, N] -> Wt [N, 1024] bf16 hi/lo (R9 version).
__global__ void conv_wt(const float* __restrict__ W0, const float* __restrict__ W1, int mode)
{
    const int z = blockIdx.z;
    const float* W = z ? W1 : W0;
    const int N = mode ? Dm : NT3;
    __nv_bfloat16* Th = mode ? g_wo_h[z] : g_wk_h[z];
    __nv_bfloat16* Tl = mode ? g_wo_l[z] : g_wk_l[z];

    __shared__ float s[32][33];
    const int n0 = blockIdx.x * 32;
    const int k0 = blockIdx.y * 32;
    const int tx = threadIdx.x, ty = threadIdx.y;
    for (int dy = ty; dy < 32; dy += 8)
        s[dy][tx] = W[(size_t)(k0 + dy) * N + n0 + tx];
    __syncthreads();
    for (int dy = ty; dy < 32; dy += 8) {
        float a = s[tx][dy];
        unsigned short h, l;
        bsplit(a, h, l);
        size_t o = (size_t)(n0 + dy) * Dm + k0 + tx;
        Th[o] = __ushort_as_bfloat16(h);
        Tl[o] = __ushort_as_bfloat16(l);
    }
}

// V transpose per head: [bh][tok][dh] -> [bh][dh][tok], 64-token tiles
__global__ __launch_bounds__(256) void vt_kernel()
{
    const int z   = blockIdx.z;
    const int bh  = blockIdx.y;
    const int kt0 = blockIdx.x * 64;
    __shared__ unsigned short s[64][68];
    const int tid = threadIdx.x;
#pragma unroll
    for (int hl = 0; hl < 2; hl++) {
        const __nv_bfloat16* in = (hl ? g_vl[z] : g_vh[z]) + (size_t)bh * Nseq * DHd;
        __nv_bfloat16* op       = (hl ? g_vtl[z] : g_vth[z]) + (size_t)bh * DHd * Nseq;
        const u32* in32 = reinterpret_cast<const u32*>(in);
        u32* out32 = reinterpret_cast<u32*>(op);
        if (hl) __syncthreads();
        for (int i = tid; i < 64 * 32; i += 256) {
            const int tok = i >> 5, dc = i & 31;
            *reinterpret_cast<u32*>(&s[tok][dc * 2]) = in32[(size_t)(kt0 + tok) * 32 + dc];
        }
        __syncthreads();
        for (int i = tid; i < 64 * 32; i += 256) {
            const int dh = i >> 5, t2 = i & 31;
            const u32 w = ((u32)s[2 * t2 + 1][dh] << 16) | (u32)s[2 * t2][dh];
            out32[(size_t)dh * (Nseq / 2) + (kt0 >> 1) + t2] = w;
        }
    }
}

// ---------------------------------------------------------------------------
// Tensor-core GEMM (R9 version; ONLY change: single-barrier 2-stage pipeline
//   {wait0; sync; issue(c+1); compute(c)} instead of two barriers per chunk).
// CTA 128x128, 8 warps (2m x 4n), m16n8k16 bf16->fp32, 3-term split
// interleaved per-(mf,nf). Fragment-direct epilogue.
// mode 0: kqv -> gated/masked bf16-split Q/K/V per-head; mode 1: proj -> fp32.
// grid (NT/128, 128, 2), block 256.
// ---------------------------------------------------------------------------
#define SMEM_MMA (2 * 65536)
extern __shared__ char dynsm[];

__global__ __launch_bounds__(256, 1) void mma_gemm(
    int mode,
    const float* __restrict__ bias0, const float* __restrict__ bias1,
    const float* __restrict__ vm, const float* __restrict__ tm,
    float* __restrict__ out)
{
    const int z   = blockIdx.z;
    const int n0  = blockIdx.x * 128;
    const int m0  = blockIdx.y * 128;
    const int tid = threadIdx.x;

    const __nv_bfloat16 *Ahp, *Alp, *Bhp, *Blp;
    float* C = nullptr;
    const float* bias = z ? bias1 : bias0;
    const float* gate = nullptr;
    const float* mk   = nullptr;
    if (mode == 0) {
        Ahp = g_ah[z]; Alp = g_al[z]; Bhp = g_wk_h[z]; Blp = g_wk_l[z];
        gate = g_gate[z]; mk = z ? tm : vm;
    } else {
        Ahp = g_ph[z]; Alp = g_pl[z]; Bhp = g_wo_h[z]; Blp = g_wo_l[z];
        C = out + (size_t)z * Mtot * Dm;
    }

    const u32 sb = s2u(dynsm);
    const int wid = tid >> 5, lane = tid & 31;
    const int wm = (wid >> 2) * 64;
    const int wn = (wid & 3) * 32;
    const int grp = lane >> 3, lr = lane & 7;
    const int a_row = ((grp & 1) << 3) + lr;
    const int a_cb  = grp >> 1;
    const int b_row = ((grp & 2) << 2) + lr;
    const int b_cb  = grp & 1;

    const int r  = tid >> 1;
    const int c0 = (tid & 1) * 4;
    const __nv_bfloat16* gAh = Ahp + (size_t)(m0 + r) * Dm;
    const __nv_bfloat16* gAl = Alp + (size_t)(m0 + r) * Dm;
    const __nv_bfloat16* gBh = Bhp + (size_t)(n0 + r) * Dm;
    const __nv_bfloat16* gBl = Blp + (size_t)(n0 + r) * Dm;

    float acc[4][4][4];
#pragma unroll
    for (int i = 0; i < 4; i++)
#pragma unroll
        for (int j = 0; j < 4; j++)
#pragma unroll
            for (int q = 0; q < 4; q++) acc[i][j][q] = 0.f;

    auto load_stage = [&](int c, int buf) {
        const u32 st = sb + buf * 65536;
        const int ko = c * 64;
#pragma unroll
        for (int j = 0; j < 4; j++) {
            const u32 so = SWZ((u32)(r * 128 + (c0 + j) * 16));
            cpa16(st + so,         gAh + ko + (c0 + j) * 8);
            cpa16(st + 16384 + so, gAl + ko + (c0 + j) * 8);
            cpa16(st + 32768 + so, gBh + ko + (c0 + j) * 8);
            cpa16(st + 49152 + so, gBl + ko + (c0 + j) * 8);
        }
    };

    load_stage(0, 0);
    cpa_commit();

    for (int c = 0; c < 16; c++) {
        cpa_wait0();
        __syncthreads();                       // also guards buf (c+1)&1 reuse
        if (c + 1 < 16) {
            load_stage(c + 1, (c + 1) & 1);
            cpa_commit();
        }

        const u32 st = sb + (c & 1) * 65536;
#pragma unroll
        for (int ks = 0; ks < 4; ks++) {
            u32 ah[4][4], al[4][4], bh[2][4], bl[2][4];
#pragma unroll
            for (int mf = 0; mf < 4; mf++) {
                const u32 off = SWZ((u32)((wm + mf * 16 + a_row) * 128 + (ks * 2 + a_cb) * 16));
                ldsm4(ah[mf][0], ah[mf][1], ah[mf][2], ah[mf][3], st + off);
                ldsm4(al[mf][0], al[mf][1], al[mf][2], al[mf][3], st + 16384 + off);
            }
#pragma unroll
            for (int np = 0; np < 2; np++) {
                const u32 off = SWZ((u32)((wn + np * 16 + b_row) * 128 + (ks * 2 + b_cb) * 16));
                ldsm4(bh[np][0], bh[np][1], bh[np][2], bh[np][3], st + 32768 + off);
                ldsm4(bl[np][0], bl[np][1], bl[np][2], bl[np][3], st + 49152 + off);
            }
#pragma unroll
            for (int mf = 0; mf < 4; mf++) {
#pragma unroll
                for (int nf = 0; nf < 4; nf++) {
                    const u32 bh0 = bh[nf >> 1][(nf & 1) * 2];
                    const u32 bh1 = bh[nf >> 1][(nf & 1) * 2 + 1];
                    const u32 bl0 = bl[nf >> 1][(nf & 1) * 2];
                    const u32 bl1 = bl[nf >> 1][(nf & 1) * 2 + 1];
                    mma16816(acc[mf][nf], ah[mf], bh0, bh1);
                    mma16816(acc[mf][nf], ah[mf], bl0, bl1);
                    mma16816(acc[mf][nf], al[mf], bh0, bh1);
                }
            }
        }
    }

    // ---- epilogue (R9 fragment-direct) ----
    const int batch = m0 >> 9;
    float bC[4][2], gC[4][2];
#pragma unroll
    for (int nf = 0; nf < 4; nf++) {
#pragma unroll
        for (int q = 0; q < 2; q++) {
            const int cc = n0 + wn + nf * 8 + (lane & 3) * 2 + q;
            bC[nf][q] = bias[cc];
            float g = 1.f;
            if (mode == 0 && cc < 2 * Dm) {
                g = 1.0f + gate[batch * Dm + (cc & (Dm - 1))];
                if (cc >= Dm) g *= 0.125f;
            }
            gC[nf][q] = g;
        }
    }

    if (mode == 0) {
        __nv_bfloat16* dH[3] = { g_kh[z], g_qh[z], g_vh[z] };
        __nv_bfloat16* dL[3] = { g_kl[z], g_ql[z], g_vl[z] };
#pragma unroll
        for (int mf = 0; mf < 4; mf++) {
            const int row0 = m0 + wm + mf * 16 + (lane >> 2);
            const int row1 = row0 + 8;
            const float mk0 = mk[batch * Nseq + (row0 & (Nseq - 1))];
            const float mk1 = mk[batch * Nseq + (row1 & (Nseq - 1))];
            const int tok0 = row0 & (Nseq - 1), tok1 = row1 & (Nseq - 1);
#pragma unroll
            for (int nf = 0; nf < 4; nf++) {
                const int col = n0 + wn + nf * 8 + (lane & 3) * 2;
                const int sec = col >> 10;
                const int d   = col & (Dm - 1);
                const int hh  = d >> 6;
                const int dh  = d & 63;
                float v00 = (acc[mf][nf][0] + bC[nf][0]) * mk0 * gC[nf][0];
                float v01 = (acc[mf][nf][1] + bC[nf][1]) * mk0 * gC[nf][1];
                float v10 = (acc[mf][nf][2] + bC[nf][0]) * mk1 * gC[nf][0];
                float v11 = (acc[mf][nf][3] + bC[nf][1]) * mk1 * gC[nf][1];
                u32 h0p, l0p, h1p, l1p;
                split_pair(v00, v01, h0p, l0p);
                split_pair(v10, v11, h1p, l1p);
                const size_t base = (size_t)(batch * Hh + hh) * Nseq;
                const size_t o0 = (base + tok0) * DHd + dh;
                const size_t o1 = (base + tok1) * DHd + dh;
                *reinterpret_cast<u32*>(dH[sec] + o0) = h0p;
                *reinterpret_cast<u32*>(dL[sec] + o0) = l0p;
                *reinterpret_cast<u32*>(dH[sec] + o1) = h1p;
                *reinterpret_cast<u32*>(dL[sec] + o1) = l1p;
            }
        }
    } else {
#pragma unroll
        for (int mf = 0; mf < 4; mf++) {
            const int row0 = m0 + wm + mf * 16 + (lane >> 2);
            const int row1 = row0 + 8;
#pragma unroll
            for (int nf = 0; nf < 4; nf++) {
                const int col = n0 + wn + nf * 8 + (lane & 3) * 2;
                float2 r0, r1;
                r0.x = acc[mf][nf][0] + bC[nf][0];
                r0.y = acc[mf][nf][1] + bC[nf][1];
                r1.x = acc[mf][nf][2] + bC[nf][0];
                r1.y = acc[mf][nf][3] + bC[nf][1];
                *reinterpret_cast<float2*>(C + (size_t)row0 * Dm + col) = r0;
                *reinterpret_cast<float2*>(C + (size_t)row1 * Dm + col) = r1;
            }
        }
    }
}

// ---------------------------------------------------------------------------
// Tensor-core flash attention (exact R9 version, the measured best).
// CTA = 128 q-rows of one (z,b,h). 8 warps x 16 q-rows. Q frags register-
// resident; K/V cp.async double-buffered; online softmax in registers;
// FA2 S->P A-frag reuse. 3-term splits. Writes g_upd.
// grid (Nseq/128=4, Hh, Bz*2), block 256. dyn smem = 100352 B.
// ---------------------------------------------------------------------------
#define ATTN_SMEM 100352

__global__ __launch_bounds__(256, 1) void attn_mma(
    const float* __restrict__ vm, const float* __restrict__ tm)
{
    const int b = blockIdx.z & (Bz - 1);
    const int z = blockIdx.z >> 5;
    const int h = blockIdx.y;
    const int q0 = blockIdx.x * 128;
    const int bh = b * Hh + h;
    const float* mk = z ? tm : vm;

    const __nv_bfloat16* Qh  = g_qh[z]  + (size_t)bh * Nseq * DHd;
    const __nv_bfloat16* Ql  = g_ql[z]  + (size_t)bh * Nseq * DHd;
    const __nv_bfloat16* Kh  = g_kh[z]  + (size_t)bh * Nseq * DHd;
    const __nv_bfloat16* Kl  = g_kl[z]  + (size_t)bh * Nseq * DHd;
    const __nv_bfloat16* Vth = g_vth[z] + (size_t)bh * DHd * Nseq;
    const __nv_bfloat16* Vtl = g_vtl[z] + (size_t)bh * DHd * Nseq;
    float* upd = z ? g_upd_t : g_upd_v;

    const u32 sb  = s2u(dynsm);
    const u32 sQh = sb;                  // 16KB
    const u32 sQl = sb + 16384;          // 16KB
    const u32 sK  = sb + 32768;          // 2 buf x (hi 8KB + lo 8KB) = 32KB
    const u32 sV  = sb + 65536;          // 32KB
    float* s_m = reinterpret_cast<float*>(dynsm + 98304);

    const int tid = threadIdx.x;
    const int wid = tid >> 5, lane = tid & 31;
    const int R = wid * 16;

    {
        const int r  = tid >> 1;
        const int e0 = (tid & 1) * 32;
#pragma unroll
        for (int i = 0; i < 4; i++) {
            const u32 so = SWZ((u32)(r * 128 + (e0 + i * 8) * 2));
            cpa16(sQh + so, Qh + (size_t)(q0 + r) * DHd + e0 + i * 8);
            cpa16(sQl + so, Ql + (size_t)(q0 + r) * DHd + e0 + i * 8);
        }
    }
    s_m[tid]       = mk[b * Nseq + tid];
    s_m[tid + 256] = mk[b * Nseq + tid + 256];
    {
        const int r  = tid >> 2;
        const int e0 = (tid & 3) * 16;
#pragma unroll
        for (int i = 0; i < 2; i++) {
            const u32 so = SWZ((u32)(r * 128 + (e0 + i * 8) * 2));
            cpa16(sK + so,        Kh  + (size_t)r * DHd + e0 + i * 8);
            cpa16(sK + 8192 + so, Kl  + (size_t)r * DHd + e0 + i * 8);
            cpa16(sV + so,        Vth + (size_t)r * Nseq + e0 + i * 8);
            cpa16(sV + 8192 + so, Vtl + (size_t)r * Nseq + e0 + i * 8);
        }
    }
    cpa_commit();
    cpa_wait0();
    __syncthreads();

    u32 qfh[4][4], qfl[4][4];
    {
        const int grp = lane >> 3, lr = lane & 7;
        const int a_row = ((grp & 1) << 3) + lr;
        const int a_cb  = grp >> 1;
#pragma unroll
        for (int kc = 0; kc < 4; kc++) {
            const u32 off = SWZ((u32)((R + a_row) * 128 + (kc * 2 + a_cb) * 16));
            ldsm4(qfh[kc][0], qfh[kc][1], qfh[kc][2], qfh[kc][3], sQh + off);
            ldsm4(qfl[kc][0], qfl[kc][1], qfl[kc][2], qfl[kc][3], sQl + off);
        }
    }

    const int grp = lane >> 3, lr = lane & 7;
    const int b_row = ((grp & 2) << 2) + lr;
    const int b_cb  = grp & 1;

    float m0r = -1e30f, m1r = -1e30f, l0r = 0.f, l1r = 0.f;
    float o[8][4];
#pragma unroll
    for (int nf = 0; nf < 8; nf++)
#pragma unroll
        for (int q = 0; q < 4; q++) o[nf][q] = 0.f;

    for (int st = 0; st < 8; st++) {
        const u32 buf = (u32)(st & 1) * 16384;
        if (st < 7) {
            const u32 nbuf = (u32)((st + 1) & 1) * 16384;
            const int kv = (st + 1) * 64;
            const int r  = tid >> 2;
            const int e0 = (tid & 3) * 16;
#pragma unroll
            for (int i = 0; i < 2; i++) {
                const u32 so = SWZ((u32)(r * 128 + (e0 + i * 8) * 2));
                cpa16(sK + nbuf + so,        Kh  + (size_t)(kv + r) * DHd + e0 + i * 8);
                cpa16(sK + nbuf + 8192 + so, Kl  + (size_t)(kv + r) * DHd + e0 + i * 8);
                cpa16(sV + nbuf + so,        Vth + (size_t)r * Nseq + kv + e0 + i * 8);
                cpa16(sV + nbuf + 8192 + so, Vtl + (size_t)r * Nseq + kv + e0 + i * 8);
            }
            cpa_commit();
            cpa_wait1();
        } else {
            cpa_wait0();
        }
        __syncthreads();

        float s[8][4];
#pragma unroll
        for (int nf = 0; nf < 8; nf++)
#pragma unroll
            for (int q = 0; q < 4; q++) s[nf][q] = 0.f;

        const u32 kb = sK + buf;
#pragma unroll
        for (int kc = 0; kc < 4; kc++) {
            u32 kh[4][4], kl[4][4];
#pragma unroll
            for (int np = 0; np < 4; np++) {
                const u32 off = SWZ((u32)((np * 16 + b_row) * 128 + (kc * 2 + b_cb) * 16));
                ldsm4(kh[np][0], kh[np][1], kh[np][2], kh[np][3], kb + off);
                ldsm4(kl[np][0], kl[np][1], kl[np][2], kl[np][3], kb + 8192 + off);
            }
#pragma unroll
            for (int np = 0; np < 4; np++) {
                mma16816(s[2 * np],     qfh[kc], kh[np][0], kh[np][1]);
                mma16816(s[2 * np],     qfh[kc], kl[np][0], kl[np][1]);
                mma16816(s[2 * np],     qfl[kc], kh[np][0], kh[np][1]);
                mma16816(s[2 * np + 1], qfh[kc], kh[np][2], kh[np][3]);
                mma16816(s[2 * np + 1], qfh[kc], kl[np][2], kl[np][3]);
                mma16816(s[2 * np + 1], qfl[kc], kh[np][2], kh[np][3]);
            }
        }

        const int cb0 = st * 64 + (lane & 3) * 2;
#pragma unroll
        for (int nf = 0; nf < 8; nf++) {
            if (s_m[cb0 + nf * 8] == 0.f)     { s[nf][0] = -1e30f; s[nf][2] = -1e30f; }
            if (s_m[cb0 + nf * 8 + 1] == 0.f) { s[nf][1] = -1e30f; s[nf][3] = -1e30f; }
        }

        float mx0 = -1e30f, mx1 = -1e30f;
#pragma unroll
        for (int nf = 0; nf < 8; nf++) {
            mx0 = fmaxf(mx0, fmaxf(s[nf][0], s[nf][1]));
            mx1 = fmaxf(mx1, fmaxf(s[nf][2], s[nf][3]));
        }
        mx0 = fmaxf(mx0, __shfl_xor_sync(0xffffffffu, mx0, 1));
        mx0 = fmaxf(mx0, __shfl_xor_sync(0xffffffffu, mx0, 2));
        mx1 = fmaxf(mx1, __shfl_xor_sync(0xffffffffu, mx1, 1));
        mx1 = fmaxf(mx1, __shfl_xor_sync(0xffffffffu, mx1, 2));

        const float nm0 = fmaxf(m0r, mx0), nm1 = fmaxf(m1r, mx1);
        const float c0 = fexp(m0r - nm0), c1 = fexp(m1r - nm1);

        float ps0 = 0.f, ps1 = 0.f;
#pragma unroll
        for (int nf = 0; nf < 8; nf++) {
            s[nf][0] = fexp(s[nf][0] - nm0); ps0 += s[nf][0];
            s[nf][1] = fexp(s[nf][1] - nm0); ps0 += s[nf][1];
            s[nf][2] = fexp(s[nf][2] - nm1); ps1 += s[nf][2];
            s[nf][3] = fexp(s[nf][3] - nm1); ps1 += s[nf][3];
        }
        ps0 += __shfl_xor_sync(0xffffffffu, ps0, 1);
        ps0 += __shfl_xor_sync(0xffffffffu, ps0, 2);
        ps1 += __shfl_xor_sync(0xffffffffu, ps1, 1);
        ps1 += __shfl_xor_sync(0xffffffffu, ps1, 2);

        l0r = l0r * c0 + ps0; m0r = nm0;
        l1r = l1r * c1 + ps1; m1r = nm1;
#pragma unroll
        for (int nf = 0; nf < 8; nf++) {
            o[nf][0] *= c0; o[nf][1] *= c0;
            o[nf][2] *= c1; o[nf][3] *= c1;
        }

        const u32 vb = sV + buf;
#pragma unroll
        for (int kc = 0; kc < 4; kc++) {
            u32 pah[4], pal[4];
            split_pair(s[2 * kc][0],     s[2 * kc][1],     pah[0], pal[0]);
            split_pair(s[2 * kc][2],     s[2 * kc][3],     pah[1], pal[1]);
            split_pair(s[2 * kc + 1][0], s[2 * kc + 1][1], pah[2], pal[2]);
            split_pair(s[2 * kc + 1][2], s[2 * kc + 1][3], pah[3], pal[3]);
#pragma unroll
            for (int np = 0; np < 4; np++) {
                const u32 off = SWZ((u32)((np * 16 + b_row) * 128 + (kc * 2 + b_cb) * 16));
                u32 vh0, vh1, vh2, vh3, vl0, vl1, vl2, vl3;
                ldsm4(vh0, vh1, vh2, vh3, vb + off);
                ldsm4(vl0, vl1, vl2, vl3, vb + 8192 + off);
                mma16816(o[2 * np],     pah, vh0, vh1);
                mma16816(o[2 * np],     pal, vh0, vh1);
                mma16816(o[2 * np],     pah, vl0, vl1);
                mma16816(o[2 * np + 1], pah, vh2, vh3);
                mma16816(o[2 * np + 1], pal, vh2, vh3);
                mma16816(o[2 * np + 1], pah, vl2, vl3);
            }
        }
        __syncthreads();
    }

    const float inv0 = 1.0f / l0r;
    const float inv1 = 1.0f / l1r;
    const int row0 = q0 + R + (lane >> 2);
    const int row1 = row0 + 8;
#pragma unroll
    for (int nf = 0; nf < 8; nf++) {
        const int d0 = nf * 8 + (lane & 3) * 2;
        float2 w0 = make_float2(o[nf][0] * inv0, o[nf][1] * inv0);
        float2 w1 = make_float2(o[nf][2] * inv1, o[nf][3] * inv1);
        *reinterpret_cast<float2*>(upd + (size_t)(b * Nseq + row0) * Dm + h * DHd + d0) = w0;
        *reinterpret_cast<float2*>(upd + (size_t)(b * Nseq + row1) * Dm + h * DHd + d0) = w1;
    }
}

// ---------------------------------------------------------------------------
// Launch (exact R9 order)
// ---------------------------------------------------------------------------
extern "C" void kernel_launch(void* const* d_in, const int* in_sizes, int n_in,
                              void* d_out, int out_size)
{
    const float* v     = (const float*)d_in[0];
    const float* t     = (const float*)d_in[1];
    const float* vm    = (const float*)d_in[2];
    const float* tm    = (const float*)d_in[3];
    const float* W_v4t = (const float*)d_in[4];
    const float* b_v4t = (const float*)d_in[5];
    const float* W_t4v = (const float*)d_in[6];
    const float* b_t4v = (const float*)d_in[7];
    const float* W_v   = (const float*)d_in[8];
    const float* b_v   = (const float*)d_in[9];
    const float* W_t   = (const float*)d_in[10];
    const float* b_t   = (const float*)d_in[11];
    const float* W_vo  = (const float*)d_in[12];
    const float* b_vo  = (const float*)d_in[13];
    const float* W_to  = (const float*)d_in[14];
    const float* b_to  = (const float*)d_in[15];
    float* out = (float*)d_out;

    cudaFuncSetAttribute(mma_gemm, cudaFuncAttributeMaxDynamicSharedMemorySize, SMEM_MMA);
    cudaFuncSetAttribute(attn_mma, cudaFuncAttributeMaxDynamicSharedMemorySize, ATTN_SMEM);

    mean_kernel<<<dim3(Dm / 256, Bz, 2), 256>>>(v, t, vm, tm);
    gate_kernel<<<dim3(Dm / 128, Bz, 2), 128>>>(W_v4t, b_v4t, W_t4v, b_t4v);

    conv_a_kqv<<<dim3(Mtot * Dm / 2048, 2), 256>>>(v, t);
    conv_wt<<<dim3(NT3 / 32, Dm / 32, 2), dim3(32, 8)>>>(W_v, W_t, 0);
    conv_wt<<<dim3(Dm / 32, Dm / 32, 2), dim3(32, 8)>>>(W_vo, W_to, 1);

    mma_gemm<<<dim3(NT3 / 128, Mtot / 128, 2), 256, SMEM_MMA>>>(
        0, b_v, b_t, vm, tm, out);

    vt_kernel<<<dim3(Nseq / 64, NBH, 2), 256>>>();

    attn_mma<<<dim3(Nseq / 128, Hh, Bz * 2), 256, ATTN_SMEM>>>(vm, tm);

    conv_a_proj<<<dim3(Mtot * Dm / 2048, 2), 256>>>(v, t);

    mma_gemm<<<dim3(Dm / 128, Mtot / 128, 2), 256, SMEM_MMA>>>(
        1, b_vo, b_to, vm, tm, out);
}

// round 16
// speedup vs baseline: 1.6312x; 1.0009x over previous
#include <cuda_runtime.h>
#include <cuda_bf16.h>
#include <cstdint>

// Problem constants
#define Bz   32
#define Nseq 512
#define Dm   1024
#define Hh   16
#define DHd  64
#define Mtot (Bz * Nseq)          // 16384
#define NT3  (3 * Dm)             // 3072

typedef unsigned long long u64;
typedef unsigned int u32;

// ---------------------------------------------------------------------------
// Scratch (allocation-free rule: __device__ globals)
// ---------------------------------------------------------------------------
__device__ float g_upd_v[Mtot * Dm];
__device__ float g_upd_t[Mtot * Dm];
__device__ float g_mean[2][Bz * Dm];
__device__ float g_gate[2][Bz * Dm];

// bf16-split operands for tensor-core GEMMs
__device__ __nv_bfloat16 g_ah[2][Mtot * Dm];   // relu(x) hi   (kqv A)
__device__ __nv_bfloat16 g_al[2][Mtot * Dm];   // relu(x) lo
__device__ __nv_bfloat16 g_ph[2][Mtot * Dm];   // (x+upd) hi   (proj A)
__device__ __nv_bfloat16 g_pl[2][Mtot * Dm];   // (x+upd) lo
__device__ __nv_bfloat16 g_wk_h[2][NT3 * Dm];  // W_v / W_t transposed [n][k] hi
__device__ __nv_bfloat16 g_wk_l[2][NT3 * Dm];
__device__ __nv_bfloat16 g_wo_h[2][Dm * Dm];   // W_vo / W_to transposed [n][k] hi
__device__ __nv_bfloat16 g_wo_l[2][Dm * Dm];

// Attention operands, per-head layout [bh][tok][64] (gated/masked, bf16 split)
#define NBH (Bz * Hh)
__device__ __nv_bfloat16 g_qh[2][NBH * Nseq * DHd];
__device__ __nv_bfloat16 g_ql[2][NBH * Nseq * DHd];
__device__ __nv_bfloat16 g_kh[2][NBH * Nseq * DHd];
__device__ __nv_bfloat16 g_kl[2][NBH * Nseq * DHd];
__device__ __nv_bfloat16 g_vh[2][NBH * Nseq * DHd];
__device__ __nv_bfloat16 g_vl[2][NBH * Nseq * DHd];
// V transposed per head: [bh][dh][tok]
__device__ __nv_bfloat16 g_vth[2][NBH * DHd * Nseq];
__device__ __nv_bfloat16 g_vtl[2][NBH * DHd * Nseq];

// ---------------------------------------------------------------------------
// Small helpers
// ---------------------------------------------------------------------------
__device__ __forceinline__ float fexp(float x) {
    x = fmaxf(x, -80.0f);
    float z  = fmaf(x, 1.4426950408889634f, 12582912.0f);
    int   ni = __float_as_int(z) - 0x4B400000;
    float nf = (float)ni;
    float r  = fmaf(nf, -0.693359375f, x);
    r        = fmaf(nf, 2.12194440e-4f, r);
    float p  = 1.9875691500e-4f;
    p = fmaf(p, r, 1.3981999507e-3f);
    p = fmaf(p, r, 8.3334519073e-3f);
    p = fmaf(p, r, 4.1665795894e-2f);
    p = fmaf(p, r, 1.6666665459e-1f);
    p = fmaf(p, r, 5.0000001201e-1f);
    float e = fmaf(r * r, p, r) + 1.0f;
    return __int_as_float(__float_as_int(e) + (ni << 23));
}

__device__ __forceinline__ void bsplit(float a, unsigned short& h, unsigned short& l) {
    __nv_bfloat16 hb = __float2bfloat16_rn(a);
    float lo = a - __bfloat162float(hb);
    __nv_bfloat16 lb = __float2bfloat16_rn(lo);
    h = __bfloat16_as_ushort(hb);
    l = __bfloat16_as_ushort(lb);
}
__device__ __forceinline__ u32 pkbf(unsigned short a, unsigned short b) {
    return ((u32)b << 16) | (u32)a;
}
__device__ __forceinline__ void split_pair(float x, float y, u32& hp, u32& lp) {
    unsigned short hx, lx, hy, ly;
    bsplit(x, hx, lx);
    bsplit(y, hy, ly);
    hp = pkbf(hx, hy);
    lp = pkbf(lx, ly);
}

__device__ __forceinline__ u32 s2u(const void* p) {
    u32 a; asm("{ .reg .u64 t; cvta.to.shared.u64 t,%1; cvt.u32.u64 %0,t; }" : "=r"(a) : "l"(p));
    return a;
}
#define SWZ(o) ((o) ^ (((o) >> 3) & 0x70))

// mma.sync / ldmatrix / cp.async wrappers (base-arch features)
__device__ __forceinline__ void ldsm4(u32& r0, u32& r1, u32& r2, u32& r3, u32 addr) {
    asm volatile("ldmatrix.sync.aligned.m8n8.x4.shared.b16 {%0,%1,%2,%3}, [%4];"
                 : "=r"(r0), "=r"(r1), "=r"(r2), "=r"(r3) : "r"(addr));
}
__device__ __forceinline__ void mma16816(float* d, const u32* a, u32 b0, u32 b1) {
    asm volatile(
        "mma.sync.aligned.m16n8k16.row.col.f32.bf16.bf16.f32 "
        "{%0,%1,%2,%3},{%4,%5,%6,%7},{%8,%9},{%0,%1,%2,%3};"
        : "+f"(d[0]), "+f"(d[1]), "+f"(d[2]), "+f"(d[3])
        : "r"(a[0]), "r"(a[1]), "r"(a[2]), "r"(a[3]), "r"(b0), "r"(b1));
}
__device__ __forceinline__ void cpa16(u32 saddr, const void* g) {
    asm volatile("cp.async.cg.shared.global [%0], [%1], 16;" :: "r"(saddr), "l"(g) : "memory");
}
__device__ __forceinline__ void cpa_commit() {
    asm volatile("cp.async.commit_group;" ::: "memory");
}
__device__ __forceinline__ void cpa_wait0() {
    asm volatile("cp.async.wait_group 0;" ::: "memory");
}

// ---------------------------------------------------------------------------
// Kernel 1: masked mean (R9 version)
// ---------------------------------------------------------------------------
__global__ __launch_bounds__(256) void mean_kernel(
    const float* __restrict__ v, const float* __restrict__ t,
    const float* __restrict__ vm, const float* __restrict__ tm)
{
    const int z = blockIdx.z;
    const int b = blockIdx.y;
    const float* X  = z ? t  : v;
    const float* mk = z ? tm : vm;

    __shared__ float s_mk[Nseq];
    __shared__ float s_red[256];

    const int tid = threadIdx.x;
    float c = 0.f;
    for (int n = tid; n < Nseq; n += 256) {
        float m = mk[b * Nseq + n];
        s_mk[n] = m;
        c += m;
    }
    s_red[tid] = c;
    __syncthreads();
    for (int s = 128; s > 0; s >>= 1) {
        if (tid < s) s_red[tid] += s_red[tid + s];
        __syncthreads();
    }
    const float inv = 1.0f / s_red[0];

    const int d = blockIdx.x * 256 + tid;
    float acc = 0.f;
    for (int n = 0; n < Nseq; n++)
        acc = fmaf(X[(size_t)(b * Nseq + n) * Dm + d], s_mk[n], acc);
    g_mean[z][b * Dm + d] = acc * inv;
}

// ---------------------------------------------------------------------------
// Kernel 2: gates (R9 version)
// ---------------------------------------------------------------------------
__global__ __launch_bounds__(128) void gate_kernel(
    const float* __restrict__ W_v4t, const float* __restrict__ b_v4t,
    const float* __restrict__ W_t4v, const float* __restrict__ b_t4v)
{
    const int z = blockIdx.z;
    const int b = blockIdx.y;
    const float* mean = g_mean[z ^ 1];
    const float* W    = z ? W_v4t : W_t4v;
    const float* bias = z ? b_v4t : b_t4v;

    __shared__ float s_m[Dm];
    const int tid = threadIdx.x;
    for (int i = tid; i < Dm; i += 128)
        s_m[i] = fmaxf(mean[b * Dm + i], 0.f);
    __syncthreads();

    const int j = blockIdx.x * 128 + tid;
    float acc = bias[j];
    for (int i = 0; i < Dm; i++)
        acc = fmaf(s_m[i], W[(size_t)i * Dm + j], acc);
    float s = 1.0f / (1.0f + fexp(-fabsf(acc)));
    g_gate[z][b * Dm + j] = (acc >= 0.f) ? s : (1.0f - s);
}

// ---------------------------------------------------------------------------
// Conversion kernels (R9 versions)
// ---------------------------------------------------------------------------
__global__ __launch_bounds__(256) void conv_a_kqv(
    const float* __restrict__ v, const float* __restrict__ t)
{
    const int z = blockIdx.y;
    const float* X = z ? t : v;
    size_t i = ((size_t)blockIdx.x * 256 + threadIdx.x) * 8;
    float4 a0 = *reinterpret_cast<const float4*>(X + i);
    float4 a1 = *reinterpret_cast<const float4*>(X + i + 4);
    float f[8] = {fmaxf(a0.x,0.f), fmaxf(a0.y,0.f), fmaxf(a0.z,0.f), fmaxf(a0.w,0.f),
                  fmaxf(a1.x,0.f), fmaxf(a1.y,0.f), fmaxf(a1.z,0.f), fmaxf(a1.w,0.f)};
    unsigned short h[8], l[8];
#pragma unroll
    for (int q = 0; q < 8; q++) bsplit(f[q], h[q], l[q]);
    uint4 H = make_uint4(pkbf(h[0],h[1]), pkbf(h[2],h[3]), pkbf(h[4],h[5]), pkbf(h[6],h[7]));
    uint4 L = make_uint4(pkbf(l[0],l[1]), pkbf(l[2],l[3]), pkbf(l[4],l[5]), pkbf(l[6],l[7]));
    *reinterpret_cast<uint4*>(&g_ah[z][i]) = H;
    *reinterpret_cast<uint4*>(&g_al[z][i]) = L;
}

__global__ __launch_bounds__(256) void conv_a_proj(
    const float* __restrict__ v, const float* __restrict__ t)
{
    const int z = blockIdx.y;
    const float* X = z ? t : v;
    const float* U = z ? g_upd_t : g_upd_v;
    size_t i = ((size_t)blockIdx.x * 256 + threadIdx.x) * 8;
    float4 a0 = *reinterpret_cast<const float4*>(X + i);
    float4 a1 = *reinterpret_cast<const float4*>(X + i + 4);
    float4 u0 = *reinterpret_cast<const float4*>(U + i);
    float4 u1 = *reinterpret_cast<const float4*>(U + i + 4);
    float f[8] = {a0.x+u0.x, a0.y+u0.y, a0.z+u0.z, a0.w+u0.w,
                  a1.x+u1.x, a1.y+u1.y, a1.z+u1.z, a1.w+u1.w};
    unsigned short h[8], l[8];
#pragma unroll
    for (int q = 0; q < 8; q++) bsplit(f[q], h[q], l[q]);
    uint4 H = make_uint4(pkbf(h[0],h[1]), pkbf(h[2],h[3]), pkbf(h[4],h[5]), pkbf(h[6],h[7]));
    uint4 L = make_uint4(pkbf(l[0],l[1]), pkbf(l[2],l[3]), pkbf(l[4],l[5]), pkbf(l[6],l[7]));
    *reinterpret_cast<uint4*>(&g_ph[z][i]) = H;
    *reinterpret_cast<uint4*>(&g_pl[z][i]) = L;
}

// Weight transpose + split: W [1024, N] -> Wt [N, 1024] bf16 hi/lo (R9 version).
__global__ void conv_wt(const float* __restrict__ W0, const float* __restrict__ W1, int mode)
{
    const int z = blockIdx.z;
    const float* W = z ? W1 : W0;
    const int N = mode ? Dm : NT3;
    __nv_bfloat16* Th = mode ? g_wo_h[z] : g_wk_h[z];
    __nv_bfloat16* Tl = mode ? g_wo_l[z] : g_wk_l[z];

    __shared__ float s[32][33];
    const int n0 = blockIdx.x * 32;
    const int k0 = blockIdx.y * 32;
    const int tx = threadIdx.x, ty = threadIdx.y;
    for (int dy = ty; dy < 32; dy += 8)
        s[dy][tx] = W[(size_t)(k0 + dy) * N + n0 + tx];
    __syncthreads();
    for (int dy = ty; dy < 32; dy += 8) {
        float a = s[tx][dy];
        unsigned short h, l;
        bsplit(a, h, l);
        size_t o = (size_t)(n0 + dy) * Dm + k0 + tx;
        Th[o] = __ushort_as_bfloat16(h);
        Tl[o] = __ushort_as_bfloat16(l);
    }
}

// V transpose per head: [bh][tok][dh] -> [bh][dh][tok], 64-token tiles
__global__ __launch_bounds__(256) void vt_kernel()
{
    const int z   = blockIdx.z;
    const int bh  = blockIdx.y;
    const int kt0 = blockIdx.x * 64;
    __shared__ unsigned short s[64][68];
    const int tid = threadIdx.x;
#pragma unroll
    for (int hl = 0; hl < 2; hl++) {
        const __nv_bfloat16* in = (hl ? g_vl[z] : g_vh[z]) + (size_t)bh * Nseq * DHd;
        __nv_bfloat16* op       = (hl ? g_vtl[z] : g_vth[z]) + (size_t)bh * DHd * Nseq;
        const u32* in32 = reinterpret_cast<const u32*>(in);
        u32* out32 = reinterpret_cast<u32*>(op);
        if (hl) __syncthreads();
        for (int i = tid; i < 64 * 32; i += 256) {
            const int tok = i >> 5, dc = i & 31;
            *reinterpret_cast<u32*>(&s[tok][dc * 2]) = in32[(size_t)(kt0 + tok) * 32 + dc];
        }
        __syncthreads();
        for (int i = tid; i < 64 * 32; i += 256) {
            const int dh = i >> 5, t2 = i & 31;
            const u32 w = ((u32)s[2 * t2 + 1][dh] << 16) | (u32)s[2 * t2][dh];
            out32[(size_t)dh * (Nseq / 2) + (kt0 >> 1) + t2] = w;
        }
    }
}

// ---------------------------------------------------------------------------
// Tensor-core GEMM (R14 version: single-barrier 2-stage pipeline
//   {wait0; sync; issue(c+1); compute(c)}).
// CTA 128x128, 8 warps (2m x 4n), m16n8k16 bf16->fp32, 3-term split
// interleaved per-(mf,nf). Fragment-direct epilogue.
// mode 0: kqv -> gated/masked bf16-split Q/K/V per-head; mode 1: proj -> fp32.
// grid (NT/128, 128, 2), block 256.
// ---------------------------------------------------------------------------
#define SMEM_MMA (2 * 65536)
extern __shared__ char dynsm[];

__global__ __launch_bounds__(256, 1) void mma_gemm(
    int mode,
    const float* __restrict__ bias0, const float* __restrict__ bias1,
    const float* __restrict__ vm, const float* __restrict__ tm,
    float* __restrict__ out)
{
    const int z   = blockIdx.z;
    const int n0  = blockIdx.x * 128;
    const int m0  = blockIdx.y * 128;
    const int tid = threadIdx.x;

    const __nv_bfloat16 *Ahp, *Alp, *Bhp, *Blp;
    float* C = nullptr;
    const float* bias = z ? bias1 : bias0;
    const float* gate = nullptr;
    const float* mk   = nullptr;
    if (mode == 0) {
        Ahp = g_ah[z]; Alp = g_al[z]; Bhp = g_wk_h[z]; Blp = g_wk_l[z];
        gate = g_gate[z]; mk = z ? tm : vm;
    } else {
        Ahp = g_ph[z]; Alp = g_pl[z]; Bhp = g_wo_h[z]; Blp = g_wo_l[z];
        C = out + (size_t)z * Mtot * Dm;
    }

    const u32 sb = s2u(dynsm);
    const int wid = tid >> 5, lane = tid & 31;
    const int wm = (wid >> 2) * 64;
    const int wn = (wid & 3) * 32;
    const int grp = lane >> 3, lr = lane & 7;
    const int a_row = ((grp & 1) << 3) + lr;
    const int a_cb  = grp >> 1;
    const int b_row = ((grp & 2) << 2) + lr;
    const int b_cb  = grp & 1;

    const int r  = tid >> 1;
    const int c0 = (tid & 1) * 4;
    const __nv_bfloat16* gAh = Ahp + (size_t)(m0 + r) * Dm;
    const __nv_bfloat16* gAl = Alp + (size_t)(m0 + r) * Dm;
    const __nv_bfloat16* gBh = Bhp + (size_t)(n0 + r) * Dm;
    const __nv_bfloat16* gBl = Blp + (size_t)(n0 + r) * Dm;

    float acc[4][4][4];
#pragma unroll
    for (int i = 0; i < 4; i++)
#pragma unroll
        for (int j = 0; j < 4; j++)
#pragma unroll
            for (int q = 0; q < 4; q++) acc[i][j][q] = 0.f;

    auto load_stage = [&](int c, int buf) {
        const u32 st = sb + buf * 65536;
        const int ko = c * 64;
#pragma unroll
        for (int j = 0; j < 4; j++) {
            const u32 so = SWZ((u32)(r * 128 + (c0 + j) * 16));
            cpa16(st + so,         gAh + ko + (c0 + j) * 8);
            cpa16(st + 16384 + so, gAl + ko + (c0 + j) * 8);
            cpa16(st + 32768 + so, gBh + ko + (c0 + j) * 8);
            cpa16(st + 49152 + so, gBl + ko + (c0 + j) * 8);
        }
    };

    load_stage(0, 0);
    cpa_commit();

    for (int c = 0; c < 16; c++) {
        cpa_wait0();
        __syncthreads();                       // also guards buf (c+1)&1 reuse
        if (c + 1 < 16) {
            load_stage(c + 1, (c + 1) & 1);
            cpa_commit();
        }

        const u32 st = sb + (c & 1) * 65536;
#pragma unroll
        for (int ks = 0; ks < 4; ks++) {
            u32 ah[4][4], al[4][4], bh[2][4], bl[2][4];
#pragma unroll
            for (int mf = 0; mf < 4; mf++) {
                const u32 off = SWZ((u32)((wm + mf * 16 + a_row) * 128 + (ks * 2 + a_cb) * 16));
                ldsm4(ah[mf][0], ah[mf][1], ah[mf][2], ah[mf][3], st + off);
                ldsm4(al[mf][0], al[mf][1], al[mf][2], al[mf][3], st + 16384 + off);
            }
#pragma unroll
            for (int np = 0; np < 2; np++) {
                const u32 off = SWZ((u32)((wn + np * 16 + b_row) * 128 + (ks * 2 + b_cb) * 16));
                ldsm4(bh[np][0], bh[np][1], bh[np][2], bh[np][3], st + 32768 + off);
                ldsm4(bl[np][0], bl[np][1], bl[np][2], bl[np][3], st + 49152 + off);
            }
#pragma unroll
            for (int mf = 0; mf < 4; mf++) {
#pragma unroll
                for (int nf = 0; nf < 4; nf++) {
                    const u32 bh0 = bh[nf >> 1][(nf & 1) * 2];
                    const u32 bh1 = bh[nf >> 1][(nf & 1) * 2 + 1];
                    const u32 bl0 = bl[nf >> 1][(nf & 1) * 2];
                    const u32 bl1 = bl[nf >> 1][(nf & 1) * 2 + 1];
                    mma16816(acc[mf][nf], ah[mf], bh0, bh1);
                    mma16816(acc[mf][nf], ah[mf], bl0, bl1);
                    mma16816(acc[mf][nf], al[mf], bh0, bh1);
                }
            }
        }
    }

    // ---- epilogue (R9 fragment-direct) ----
    const int batch = m0 >> 9;
    float bC[4][2], gC[4][2];
#pragma unroll
    for (int nf = 0; nf < 4; nf++) {
#pragma unroll
        for (int q = 0; q < 2; q++) {
            const int cc = n0 + wn + nf * 8 + (lane & 3) * 2 + q;
            bC[nf][q] = bias[cc];
            float g = 1.f;
            if (mode == 0 && cc < 2 * Dm) {
                g = 1.0f + gate[batch * Dm + (cc & (Dm - 1))];
                if (cc >= Dm) g *= 0.125f;
            }
            gC[nf][q] = g;
        }
    }

    if (mode == 0) {
        __nv_bfloat16* dH[3] = { g_kh[z], g_qh[z], g_vh[z] };
        __nv_bfloat16* dL[3] = { g_kl[z], g_ql[z], g_vl[z] };
#pragma unroll
        for (int mf = 0; mf < 4; mf++) {
            const int row0 = m0 + wm + mf * 16 + (lane >> 2);
            const int row1 = row0 + 8;
            const float mk0 = mk[batch * Nseq + (row0 & (Nseq - 1))];
            const float mk1 = mk[batch * Nseq + (row1 & (Nseq - 1))];
            const int tok0 = row0 & (Nseq - 1), tok1 = row1 & (Nseq - 1);
#pragma unroll
            for (int nf = 0; nf < 4; nf++) {
                const int col = n0 + wn + nf * 8 + (lane & 3) * 2;
                const int sec = col >> 10;
                const int d   = col & (Dm - 1);
                const int hh  = d >> 6;
                const int dh  = d & 63;
                float v00 = (acc[mf][nf][0] + bC[nf][0]) * mk0 * gC[nf][0];
                float v01 = (acc[mf][nf][1] + bC[nf][1]) * mk0 * gC[nf][1];
                float v10 = (acc[mf][nf][2] + bC[nf][0]) * mk1 * gC[nf][0];
                float v11 = (acc[mf][nf][3] + bC[nf][1]) * mk1 * gC[nf][1];
                u32 h0p, l0p, h1p, l1p;
                split_pair(v00, v01, h0p, l0p);
                split_pair(v10, v11, h1p, l1p);
                const size_t base = (size_t)(batch * Hh + hh) * Nseq;
                const size_t o0 = (base + tok0) * DHd + dh;
                const size_t o1 = (base + tok1) * DHd + dh;
                *reinterpret_cast<u32*>(dH[sec] + o0) = h0p;
                *reinterpret_cast<u32*>(dL[sec] + o0) = l0p;
                *reinterpret_cast<u32*>(dH[sec] + o1) = h1p;
                *reinterpret_cast<u32*>(dL[sec] + o1) = l1p;
            }
        }
    } else {
#pragma unroll
        for (int mf = 0; mf < 4; mf++) {
            const int row0 = m0 + wm + mf * 16 + (lane >> 2);
            const int row1 = row0 + 8;
#pragma unroll
            for (int nf = 0; nf < 4; nf++) {
                const int col = n0 + wn + nf * 8 + (lane & 3) * 2;
                float2 r0, r1;
                r0.x = acc[mf][nf][0] + bC[nf][0];
                r0.y = acc[mf][nf][1] + bC[nf][1];
                r1.x = acc[mf][nf][2] + bC[nf][0];
                r1.y = acc[mf][nf][3] + bC[nf][1];
                *reinterpret_cast<float2*>(C + (size_t)row0 * Dm + col) = r0;
                *reinterpret_cast<float2*>(C + (size_t)row1 * Dm + col) = r1;
            }
        }
    }
}

// ---------------------------------------------------------------------------
// Tensor-core flash attention (R9 base; ONLY change: single-barrier pipeline
//   {wait0; sync; issue(st+1); compute(st)} — 8 barriers instead of 16).
// Buffer-reuse safety: sync at step st proves compute(st-1) done before
// issue(st+1) overwrites buffer (st+1)&1 == (st-1)&1.
// grid (Nseq/128=4, Hh, Bz*2), block 256. dyn smem = 100352 B.
// ---------------------------------------------------------------------------
#define ATTN_SMEM 100352

__global__ __launch_bounds__(256, 1) void attn_mma(
    const float* __restrict__ vm, const float* __restrict__ tm)
{
    const int b = blockIdx.z & (Bz - 1);
    const int z = blockIdx.z >> 5;
    const int h = blockIdx.y;
    const int q0 = blockIdx.x * 128;
    const int bh = b * Hh + h;
    const float* mk = z ? tm : vm;

    const __nv_bfloat16* Qh  = g_qh[z]  + (size_t)bh * Nseq * DHd;
    const __nv_bfloat16* Ql  = g_ql[z]  + (size_t)bh * Nseq * DHd;
    const __nv_bfloat16* Kh  = g_kh[z]  + (size_t)bh * Nseq * DHd;
    const __nv_bfloat16* Kl  = g_kl[z]  + (size_t)bh * Nseq * DHd;
    const __nv_bfloat16* Vth = g_vth[z] + (size_t)bh * DHd * Nseq;
    const __nv_bfloat16* Vtl = g_vtl[z] + (size_t)bh * DHd * Nseq;
    float* upd = z ? g_upd_t : g_upd_v;

    const u32 sb  = s2u(dynsm);
    const u32 sQh = sb;                  // 16KB
    const u32 sQl = sb + 16384;          // 16KB
    const u32 sK  = sb + 32768;          // 2 buf x (hi 8KB + lo 8KB) = 32KB
    const u32 sV  = sb + 65536;          // 32KB
    float* s_m = reinterpret_cast<float*>(dynsm + 98304);

    const int tid = threadIdx.x;
    const int wid = tid >> 5, lane = tid & 31;
    const int R = wid * 16;

    {
        const int r  = tid >> 1;
        const int e0 = (tid & 1) * 32;
#pragma unroll
        for (int i = 0; i < 4; i++) {
            const u32 so = SWZ((u32)(r * 128 + (e0 + i * 8) * 2));
            cpa16(sQh + so, Qh + (size_t)(q0 + r) * DHd + e0 + i * 8);
            cpa16(sQl + so, Ql + (size_t)(q0 + r) * DHd + e0 + i * 8);
        }
    }
    s_m[tid]       = mk[b * Nseq + tid];
    s_m[tid + 256] = mk[b * Nseq + tid + 256];
    {
        const int r  = tid >> 2;
        const int e0 = (tid & 3) * 16;
#pragma unroll
        for (int i = 0; i < 2; i++) {
            const u32 so = SWZ((u32)(r * 128 + (e0 + i * 8) * 2));
            cpa16(sK + so,        Kh  + (size_t)r * DHd + e0 + i * 8);
            cpa16(sK + 8192 + so, Kl  + (size_t)r * DHd + e0 + i * 8);
            cpa16(sV + so,        Vth + (size_t)r * Nseq + e0 + i * 8);
            cpa16(sV + 8192 + so, Vtl + (size_t)r * Nseq + e0 + i * 8);
        }
    }
    cpa_commit();
    cpa_wait0();
    __syncthreads();

    u32 qfh[4][4], qfl[4][4];
    {
        const int grp = lane >> 3, lr = lane & 7;
        const int a_row = ((grp & 1) << 3) + lr;
        const int a_cb  = grp >> 1;
#pragma unroll
        for (int kc = 0; kc < 4; kc++) {
            const u32 off = SWZ((u32)((R + a_row) * 128 + (kc * 2 + a_cb) * 16));
            ldsm4(qfh[kc][0], qfh[kc][1], qfh[kc][2], qfh[kc][3], sQh + off);
            ldsm4(qfl[kc][0], qfl[kc][1], qfl[kc][2], qfl[kc][3], sQl + off);
        }
    }

    const int grp = lane >> 3, lr = lane & 7;
    const int b_row = ((grp & 2) << 2) + lr;
    const int b_cb  = grp & 1;

    float m0r = -1e30f, m1r = -1e30f, l0r = 0.f, l1r = 0.f;
    float o[8][4];
#pragma unroll
    for (int nf = 0; nf < 8; nf++)
#pragma unroll
        for (int q = 0; q < 4; q++) o[nf][q] = 0.f;

    for (int st = 0; st < 8; st++) {
        const u32 buf = (u32)(st & 1) * 16384;
        if (st > 0) {
            cpa_wait0();
            __syncthreads();                   // also guards buf (st+1)&1 reuse
        }
        if (st + 1 < 8) {
            const u32 nbuf = (u32)((st + 1) & 1) * 16384;
            const int kv = (st + 1) * 64;
            const int r  = tid >> 2;
            const int e0 = (tid & 3) * 16;
#pragma unroll
            for (int i = 0; i < 2; i++) {
                const u32 so = SWZ((u32)(r * 128 + (e0 + i * 8) * 2));
                cpa16(sK + nbuf + so,        Kh  + (size_t)(kv + r) * DHd + e0 + i * 8);
                cpa16(sK + nbuf + 8192 + so, Kl  + (size_t)(kv + r) * DHd + e0 + i * 8);
                cpa16(sV + nbuf + so,        Vth + (size_t)r * Nseq + kv + e0 + i * 8);
                cpa16(sV + nbuf + 8192 + so, Vtl + (size_t)r * Nseq + kv + e0 + i * 8);
            }
            cpa_commit();
        }

        float s[8][4];
#pragma unroll
        for (int nf = 0; nf < 8; nf++)
#pragma unroll
            for (int q = 0; q < 4; q++) s[nf][q] = 0.f;

        const u32 kb = sK + buf;
#pragma unroll
        for (int kc = 0; kc < 4; kc++) {
            u32 kh[4][4], kl[4][4];
#pragma unroll
            for (int np = 0; np < 4; np++) {
                const u32 off = SWZ((u32)((np * 16 + b_row) * 128 + (kc * 2 + b_cb) * 16));
                ldsm4(kh[np][0], kh[np][1], kh[np][2], kh[np][3], kb + off);
                ldsm4(kl[np][0], kl[np][1], kl[np][2], kl[np][3], kb + 8192 + off);
            }
#pragma unroll
            for (int np = 0; np < 4; np++) {
                mma16816(s[2 * np],     qfh[kc], kh[np][0], kh[np][1]);
                mma16816(s[2 * np],     qfh[kc], kl[np][0], kl[np][1]);
                mma16816(s[2 * np],     qfl[kc], kh[np][0], kh[np][1]);
                mma16816(s[2 * np + 1], qfh[kc], kh[np][2], kh[np][3]);
                mma16816(s[2 * np + 1], qfh[kc], kl[np][2], kl[np][3]);
                mma16816(s[2 * np + 1], qfl[kc], kh[np][2], kh[np][3]);
            }
        }

        const int cb0 = st * 64 + (lane & 3) * 2;
#pragma unroll
        for (int nf = 0; nf < 8; nf++) {
            if (s_m[cb0 + nf * 8] == 0.f)     { s[nf][0] = -1e30f; s[nf][2] = -1e30f; }
            if (s_m[cb0 + nf * 8 + 1] == 0.f) { s[nf][1] = -1e30f; s[nf][3] = -1e30f; }
        }

        float mx0 = -1e30f, mx1 = -1e30f;
#pragma unroll
        for (int nf = 0; nf < 8; nf++) {
            mx0 = fmaxf(mx0, fmaxf(s[nf][0], s[nf][1]));
            mx1 = fmaxf(mx1, fmaxf(s[nf][2], s[nf][3]));
        }
        mx0 = fmaxf(mx0, __shfl_xor_sync(0xffffffffu, mx0, 1));
        mx0 = fmaxf(mx0, __shfl_xor_sync(0xffffffffu, mx0, 2));
        mx1 = fmaxf(mx1, __shfl_xor_sync(0xffffffffu, mx1, 1));
        mx1 = fmaxf(mx1, __shfl_xor_sync(0xffffffffu, mx1, 2));

        const float nm0 = fmaxf(m0r, mx0), nm1 = fmaxf(m1r, mx1);
        const float c0 = fexp(m0r - nm0), c1 = fexp(m1r - nm1);

        float ps0 = 0.f, ps1 = 0.f;
#pragma unroll
        for (int nf = 0; nf < 8; nf++) {
            s[nf][0] = fexp(s[nf][0] - nm0); ps0 += s[nf][0];
            s[nf][1] = fexp(s[nf][1] - nm0); ps0 += s[nf][1];
            s[nf][2] = fexp(s[nf][2] - nm1); ps1 += s[nf][2];
            s[nf][3] = fexp(s[nf][3] - nm1); ps1 += s[nf][3];
        }
        ps0 += __shfl_xor_sync(0xffffffffu, ps0, 1);
        ps0 += __shfl_xor_sync(0xffffffffu, ps0, 2);
        ps1 += __shfl_xor_sync(0xffffffffu, ps1, 1);
        ps1 += __shfl_xor_sync(0xffffffffu, ps1, 2);

        l0r = l0r * c0 + ps0; m0r = nm0;
        l1r = l1r * c1 + ps1; m1r = nm1;
#pragma unroll
        for (int nf = 0; nf < 8; nf++) {
            o[nf][0] *= c0; o[nf][1] *= c0;
            o[nf][2] *= c1; o[nf][3] *= c1;
        }

        const u32 vb = sV + buf;
#pragma unroll
        for (int kc = 0; kc < 4; kc++) {
            u32 pah[4], pal[4];
            split_pair(s[2 * kc][0],     s[2 * kc][1],     pah[0], pal[0]);
            split_pair(s[2 * kc][2],     s[2 * kc][3],     pah[1], pal[1]);
            split_pair(s[2 * kc + 1][0], s[2 * kc + 1][1], pah[2], pal[2]);
            split_pair(s[2 * kc + 1][2], s[2 * kc + 1][3], pah[3], pal[3]);
#pragma unroll
            for (int np = 0; np < 4; np++) {
                const u32 off = SWZ((u32)((np * 16 + b_row) * 128 + (kc * 2 + b_cb) * 16));
                u32 vh0, vh1, vh2, vh3, vl0, vl1, vl2, vl3;
                ldsm4(vh0, vh1, vh2, vh3, vb + off);
                ldsm4(vl0, vl1, vl2, vl3, vb + 8192 + off);
                mma16816(o[2 * np],     pah, vh0, vh1);
                mma16816(o[2 * np],     pal, vh0, vh1);
                mma16816(o[2 * np],     pah, vl0, vl1);
                mma16816(o[2 * np + 1], pah, vh2, vh3);
                mma16816(o[2 * np + 1], pal, vh2, vh3);
                mma16816(o[2 * np + 1], pah, vl2, vl3);
            }
        }
    }

    const float inv0 = 1.0f / l0r;
    const float inv1 = 1.0f / l1r;
    const int row0 = q0 + R + (lane >> 2);
    const int row1 = row0 + 8;
#pragma unroll
    for (int nf = 0; nf < 8; nf++) {
        const int d0 = nf * 8 + (lane & 3) * 2;
        float2 w0 = make_float2(o[nf][0] * inv0, o[nf][1] * inv0);
        float2 w1 = make_float2(o[nf][2] * inv1, o[nf][3] * inv1);
        *reinterpret_cast<float2*>(upd + (size_t)(b * Nseq + row0) * Dm + h * DHd + d0) = w0;
        *reinterpret_cast<float2*>(upd + (size_t)(b * Nseq + row1) * Dm + h * DHd + d0) = w1;
    }
}

// ---------------------------------------------------------------------------
// Launch (exact R9/R14 order)
// ---------------------------------------------------------------------------
extern "C" void kernel_launch(void* const* d_in, const int* in_sizes, int n_in,
                              void* d_out, int out_size)
{
    const float* v     = (const float*)d_in[0];
    const float* t     = (const float*)d_in[1];
    const float* vm    = (const float*)d_in[2];
    const float* tm    = (const float*)d_in[3];
    const float* W_v4t = (const float*)d_in[4];
    const float* b_v4t = (const float*)d_in[5];
    const float* W_t4v = (const float*)d_in[6];
    const float* b_t4v = (const float*)d_in[7];
    const float* W_v   = (const float*)d_in[8];
    const float* b_v   = (const float*)d_in[9];
    const float* W_t   = (const float*)d_in[10];
    const float* b_t   = (const float*)d_in[11];
    const float* W_vo  = (const float*)d_in[12];
    const float* b_vo  = (const float*)d_in[13];
    const float* W_to  = (const float*)d_in[14];
    const float* b_to  = (const float*)d_in[15];
    float* out = (float*)d_out;

    cudaFuncSetAttribute(mma_gemm, cudaFuncAttributeMaxDynamicSharedMemorySize, SMEM_MMA);
    cudaFuncSetAttribute(attn_mma, cudaFuncAttributeMaxDynamicSharedMemorySize, ATTN_SMEM);

    mean_kernel<<<dim3(Dm / 256, Bz, 2), 256>>>(v, t, vm, tm);
    gate_kernel<<<dim3(Dm / 128, Bz, 2), 128>>>(W_v4t, b_v4t, W_t4v, b_t4v);

    conv_a_kqv<<<dim3(Mtot * Dm / 2048, 2), 256>>>(v, t);
    conv_wt<<<dim3(NT3 / 32, Dm / 32, 2), dim3(32, 8)>>>(W_v, W_t, 0);
    conv_wt<<<dim3(Dm / 32, Dm / 32, 2), dim3(32, 8)>>>(W_vo, W_to, 1);

    mma_gemm<<<dim3(NT3 / 128, Mtot / 128, 2), 256, SMEM_MMA>>>(
        0, b_v, b_t, vm, tm, out);

    vt_kernel<<<dim3(Nseq / 64, NBH, 2), 256>>>();

    attn_mma<<<dim3(Nseq / 128, Hh, Bz * 2), 256, ATTN_SMEM>>>(vm, tm);

    conv_a_proj<<<dim3(Mtot * Dm / 2048, 2), 256>>>(v, t);

    mma_gemm<<<dim3(Dm / 128, Mtot / 128, 2), 256, SMEM_MMA>>>(
        1, b_vo, b_to, vm, tm, out);
}